// round 10
// baseline (speedup 1.0000x reference)
#include <cuda_runtime.h>
#include <math.h>
#include <stdint.h>

#define HEADS   8
#define DIMV    384
#define HD      48
#define ADLAV   343
#define HWD     14
#define NTOK    2744
#define BATCH   8
#define SCALEV  0.14433756729740645f   // 48^-0.5
#define LG2PAD  352                    // padded row stride for attn2 logits

#define BN_TOT  (BATCH * NTOK)         // 21952

// ---------------- scratch (static device allocations) ------------------------
__device__ float g_q[BATCH * NTOK * DIMV];
__device__ float g_kv[BATCH * NTOK * 2 * DIMV];
__device__ float g_adla[BATCH * ADLAV * DIMV];
__device__ float g_bias1[HEADS * ADLAV * NTOK];
__device__ float g_bias2[HEADS * ADLAV * NTOK];      // [h,a,n]
__device__ float g_bias2t[HEADS * ADLAV * NTOK];     // [h,n,a]
__device__ float g_logits[BATCH * HEADS * NTOK * LG2PAD];  // raw logits, reused
__device__ float g_adlav[BATCH * HEADS * ADLAV * HD];
__device__ float g_attnout[BATCH * NTOK * DIMV];

// ---------------- tf32 helpers ----------------------------------------------
__device__ __forceinline__ uint32_t f2tf32(float x) {
    uint32_t r;
    asm("cvt.rna.tf32.f32 %0, %1;" : "=r"(r) : "f"(x));
    return r;
}

__device__ __forceinline__ void mma_tf32(float* c, const uint32_t* a, const uint32_t* b) {
    asm volatile(
        "mma.sync.aligned.m16n8k8.row.col.f32.tf32.tf32.f32 "
        "{%0,%1,%2,%3}, {%4,%5,%6,%7}, {%8,%9}, {%0,%1,%2,%3};\n"
        : "+f"(c[0]), "+f"(c[1]), "+f"(c[2]), "+f"(c[3])
        : "r"(a[0]), "r"(a[1]), "r"(a[2]), "r"(a[3]), "r"(b[0]), "r"(b[1]));
}

// ============ tgemm64: tile 128x64, BK=16 (logits GEMMs) =====================
// Bias now has BOTH z-slot strides (bBib for z>>3 slot, bBih for z&7 slot) so
// callers can reorder z head-major for L2 bias reuse.
#define BMT 128
#define BNT 64
#define BKT 16
#define PA 136
#define PB 72
__global__ __launch_bounds__(256) void tgemm64(int M, int N, int K,
    const float* __restrict__ A, long long rsA, long long csA, long long bAb, long long bAh,
    const float* __restrict__ B, long long rsB, long long csB, long long bBb, long long bBh,
    float* __restrict__ C, long long rsC, long long csC, long long bCb, long long bCh,
    const float* __restrict__ Bi, long long rsBi, long long csBi, long long bBib, long long bBih,
    float alpha)
{
    __shared__ uint32_t As[2][BKT][PA];
    __shared__ uint32_t Bs[2][BKT][PB];

    int z  = blockIdx.z;
    int bb = z >> 3;
    int hh = z & 7;
    const float* Ab = A + (long long)bb * bAb + (long long)hh * bAh;
    const float* Bb = B + (long long)bb * bBb + (long long)hh * bBh;
    float*       Cb = C + (long long)bb * bCb + (long long)hh * bCh;
    const float* Bib = Bi ? (Bi + (long long)bb * bBib + (long long)hh * bBih) : nullptr;

    int m0 = blockIdx.y * BMT;
    int n0 = blockIdx.x * BNT;
    int tid  = threadIdx.x;
    int warp = tid >> 5;
    int lane = tid & 31;
    int g  = lane >> 2;
    int tg = lane & 3;
    int wm = warp & 3;
    int wn = warp >> 2;
    int mW = wm * 32;
    int nW = wn * 32;

    int amM = tid & 127;
    int akq = tid >> 7;
    int bnKK = tid >> 4;
    int bnNQ = tid & 15;
    int bkN  = tid & 63;
    int bkKQ = tid >> 6;
    const bool bContigN = (csB == 1);

    float acc[2][4][4];
    #pragma unroll
    for (int i = 0; i < 2; i++)
        #pragma unroll
        for (int j = 0; j < 4; j++)
            #pragma unroll
            for (int l = 0; l < 4; l++) acc[i][j][l] = 0.f;

    float4 va[2], vb;

    auto loadTile = [&](int k0) {
        #pragma unroll
        for (int i = 0; i < 2; i++) {
            int kq = akq + i * 2;
            int gm = m0 + amM, gk = k0 + kq * 4;
            float4 v = make_float4(0.f, 0.f, 0.f, 0.f);
            if (gm < M) {
                if (csA == 1 && gk + 4 <= K) {
                    v = *(const float4*)(Ab + (long long)gm * rsA + gk);
                } else {
                    float* pv = (float*)&v;
                    #pragma unroll
                    for (int j = 0; j < 4; j++)
                        if (gk + j < K) pv[j] = Ab[(long long)gm * rsA + (long long)(gk + j) * csA];
                }
            }
            va[i] = v;
        }
        float4 v = make_float4(0.f, 0.f, 0.f, 0.f);
        if (bContigN) {
            int gk = k0 + bnKK, gn = n0 + bnNQ * 4;
            if (gk < K) {
                if (gn + 4 <= N) {
                    v = *(const float4*)(Bb + (long long)gk * rsB + gn);
                } else {
                    float* pv = (float*)&v;
                    #pragma unroll
                    for (int j = 0; j < 4; j++)
                        if (gn + j < N) pv[j] = Bb[(long long)gk * rsB + (long long)(gn + j)];
                }
            }
        } else {
            int gn = n0 + bkN, gk = k0 + bkKQ * 4;
            if (gn < N) {
                if (rsB == 1 && gk + 4 <= K) {
                    v = *(const float4*)(Bb + (long long)gn * csB + gk);
                } else {
                    float* pv = (float*)&v;
                    #pragma unroll
                    for (int j = 0; j < 4; j++)
                        if (gk + j < K) pv[j] = Bb[(long long)(gk + j) * rsB + (long long)gn * csB];
                }
            }
        }
        vb = v;
    };

    auto storeTile = [&](int bsel) {
        #pragma unroll
        for (int i = 0; i < 2; i++) {
            int kq = akq + i * 2;
            const float* pv = (const float*)&va[i];
            #pragma unroll
            for (int j = 0; j < 4; j++)
                As[bsel][kq * 4 + j][amM] = f2tf32(pv[j]);
        }
        const float* pv = (const float*)&vb;
        if (bContigN) {
            uint4 u;
            u.x = f2tf32(pv[0]); u.y = f2tf32(pv[1]);
            u.z = f2tf32(pv[2]); u.w = f2tf32(pv[3]);
            *(uint4*)&Bs[bsel][bnKK][bnNQ * 4] = u;
        } else {
            #pragma unroll
            for (int j = 0; j < 4; j++)
                Bs[bsel][bkKQ * 4 + j][bkN] = f2tf32(pv[j]);
        }
    };

    auto compute = [&](int bsel) {
        #pragma unroll
        for (int ks = 0; ks < 2; ks++) {
            int kk = ks * 8;
            uint32_t af[2][4];
            #pragma unroll
            for (int mi = 0; mi < 2; mi++) {
                int mb = mW + mi * 16;
                af[mi][0] = As[bsel][kk + tg][mb + g];
                af[mi][1] = As[bsel][kk + tg][mb + g + 8];
                af[mi][2] = As[bsel][kk + tg + 4][mb + g];
                af[mi][3] = As[bsel][kk + tg + 4][mb + g + 8];
            }
            uint32_t bf[4][2];
            #pragma unroll
            for (int ni = 0; ni < 4; ni++) {
                int nb = nW + ni * 8;
                bf[ni][0] = Bs[bsel][kk + tg][nb + g];
                bf[ni][1] = Bs[bsel][kk + tg + 4][nb + g];
            }
            #pragma unroll
            for (int mi = 0; mi < 2; mi++)
                #pragma unroll
                for (int ni = 0; ni < 4; ni++)
                    mma_tf32(acc[mi][ni], af[mi], bf[ni]);
        }
    };

    int nk = (K + BKT - 1) / BKT;
    loadTile(0);
    storeTile(0);
    __syncthreads();
    int buf = 0;
    for (int i = 0; i < nk; i++) {
        if (i + 1 < nk) loadTile((i + 1) * BKT);
        compute(buf);
        if (i + 1 < nk) {
            storeTile(buf ^ 1);
            buf ^= 1;
            __syncthreads();
        }
    }

    bool vecC = (csC == 1) && ((rsC & 1) == 0);
    #pragma unroll
    for (int mi = 0; mi < 2; mi++) {
        #pragma unroll
        for (int ni = 0; ni < 4; ni++) {
            #pragma unroll
            for (int half = 0; half < 2; half++) {
                int r = m0 + mW + mi * 16 + g + half * 8;
                if (r >= M) continue;
                int c = n0 + nW + ni * 8 + tg * 2;
                float v0 = alpha * acc[mi][ni][half * 2];
                float v1 = alpha * acc[mi][ni][half * 2 + 1];
                if (Bib) {
                    if (c < N)     v0 += Bib[(long long)r * rsBi + (long long)c * csBi];
                    if (c + 1 < N) v1 += Bib[(long long)r * rsBi + (long long)(c + 1) * csBi];
                }
                if (vecC && c + 2 <= N) {
                    float2 w; w.x = v0; w.y = v1;
                    *(float2*)(Cb + (long long)r * rsC + c) = w;
                } else {
                    if (c < N)     Cb[(long long)r * rsC + (long long)c * csC] = v0;
                    if (c + 1 < N) Cb[(long long)r * rsC + (long long)(c + 1) * csC] = v1;
                }
            }
        }
    }
}

// ============ pv_fused: softmax(raw logits) @ V, tile 128x64 =================
// A = raw logits rows (csA=1). Prologue computes exact per-row max and exp-sum
// (same math as the standalone softmax), then the A smem fill applies
// p = exp(s - m) / l before tf32 quantization. B/C contiguous (cs=1).
__global__ __launch_bounds__(256) void pv_fused(int M, int N, int K,
    const float* __restrict__ A, int rsA, long long bAb, long long bAh,
    const float* __restrict__ B, int rsB, long long bBb, long long bBh,
    float* __restrict__ C, int rsC, long long bCb, long long bCh)
{
    __shared__ uint32_t As[2][BKT][PA];
    __shared__ uint32_t Bs[2][BKT][PB];
    __shared__ float sM[BMT], sInvL[BMT];

    int z  = blockIdx.z;
    int bb = z >> 3;
    int hh = z & 7;
    const float* Ab = A + (long long)bb * bAb + (long long)hh * bAh;
    const float* Bb = B + (long long)bb * bBb + (long long)hh * bBh;
    float*       Cb = C + (long long)bb * bCb + (long long)hh * bCh;

    int m0 = blockIdx.y * BMT;
    int n0 = blockIdx.x * BNT;
    int tid  = threadIdx.x;
    int warp = tid >> 5;
    int lane = tid & 31;
    int g  = lane >> 2;
    int tg = lane & 3;
    int wm = warp & 3;
    int wn = warp >> 2;
    int mW = wm * 32;
    int nW = wn * 32;

    // ---- softmax stats for this m-tile's rows ----
    for (int r = warp; r < BMT; r += 8) {
        int gr = m0 + r;
        float mx = -1e30f, sum = 0.f;
        if (gr < M) {
            const float* row = Ab + (long long)gr * rsA;
            int K4 = K >> 2;
            const float4* row4 = (const float4*)row;
            for (int c = lane; c < K4; c += 32) {
                float4 v = row4[c];
                mx = fmaxf(mx, fmaxf(fmaxf(v.x, v.y), fmaxf(v.z, v.w)));
            }
            for (int c = (K4 << 2) + lane; c < K; c += 32) mx = fmaxf(mx, row[c]);
            #pragma unroll
            for (int s2 = 16; s2 > 0; s2 >>= 1) mx = fmaxf(mx, __shfl_xor_sync(0xffffffffu, mx, s2));
            for (int c = lane; c < K4; c += 32) {
                float4 v = row4[c];
                sum += __expf(v.x - mx) + __expf(v.y - mx)
                     + __expf(v.z - mx) + __expf(v.w - mx);
            }
            for (int c = (K4 << 2) + lane; c < K; c += 32) sum += __expf(row[c] - mx);
            #pragma unroll
            for (int s2 = 16; s2 > 0; s2 >>= 1) sum += __shfl_xor_sync(0xffffffffu, sum, s2);
        }
        if (lane == 0) { sM[r] = mx; sInvL[r] = (gr < M) ? (1.f / sum) : 0.f; }
    }
    __syncthreads();

    int amM = tid & 127;
    int akq = tid >> 7;
    int bnKK = tid >> 4;
    int bnNQ = tid & 15;
    bool rowOk = (m0 + amM) < M;

    float acc[2][4][4];
    #pragma unroll
    for (int i = 0; i < 2; i++)
        #pragma unroll
        for (int j = 0; j < 4; j++)
            #pragma unroll
            for (int l = 0; l < 4; l++) acc[i][j][l] = 0.f;

    float4 va[2], vb;

    auto loadTile = [&](int k0) {
        #pragma unroll
        for (int i = 0; i < 2; i++) {
            int kq = akq + i * 2;
            int gm = m0 + amM, gk = k0 + kq * 4;
            float4 v = make_float4(0.f, 0.f, 0.f, 0.f);
            if (gm < M) {
                if (gk + 4 <= K) {
                    v = *(const float4*)(Ab + (long long)gm * rsA + gk);
                } else {
                    float* pv = (float*)&v;
                    #pragma unroll
                    for (int j = 0; j < 4; j++)
                        if (gk + j < K) pv[j] = Ab[(long long)gm * rsA + gk + j];
                }
            }
            va[i] = v;
        }
        float4 v = make_float4(0.f, 0.f, 0.f, 0.f);
        int gk = k0 + bnKK, gn = n0 + bnNQ * 4;
        if (gk < K) {
            if (gn + 4 <= N) {
                v = *(const float4*)(Bb + (long long)gk * rsB + gn);
            } else {
                float* pv = (float*)&v;
                #pragma unroll
                for (int j = 0; j < 4; j++)
                    if (gn + j < N) pv[j] = Bb[(long long)gk * rsB + (long long)(gn + j)];
            }
        }
        vb = v;
    };

    auto storeTile = [&](int bsel, int k0) {
        float mrow = sM[amM];
        float irow = sInvL[amM];
        #pragma unroll
        for (int i = 0; i < 2; i++) {
            int kq = akq + i * 2;
            int gk = k0 + kq * 4;
            const float* pv = (const float*)&va[i];
            #pragma unroll
            for (int j = 0; j < 4; j++) {
                uint32_t u = 0u;
                if (rowOk && gk + j < K)
                    u = f2tf32(__expf(pv[j] - mrow) * irow);
                As[bsel][kq * 4 + j][amM] = u;
            }
        }
        const float* pv = (const float*)&vb;
        uint4 u;
        u.x = f2tf32(pv[0]); u.y = f2tf32(pv[1]);
        u.z = f2tf32(pv[2]); u.w = f2tf32(pv[3]);
        *(uint4*)&Bs[bsel][bnKK][bnNQ * 4] = u;
    };

    auto compute = [&](int bsel) {
        #pragma unroll
        for (int ks = 0; ks < 2; ks++) {
            int kk = ks * 8;
            uint32_t af[2][4];
            #pragma unroll
            for (int mi = 0; mi < 2; mi++) {
                int mb = mW + mi * 16;
                af[mi][0] = As[bsel][kk + tg][mb + g];
                af[mi][1] = As[bsel][kk + tg][mb + g + 8];
                af[mi][2] = As[bsel][kk + tg + 4][mb + g];
                af[mi][3] = As[bsel][kk + tg + 4][mb + g + 8];
            }
            uint32_t bf[4][2];
            #pragma unroll
            for (int ni = 0; ni < 4; ni++) {
                int nb = nW + ni * 8;
                bf[ni][0] = Bs[bsel][kk + tg][nb + g];
                bf[ni][1] = Bs[bsel][kk + tg + 4][nb + g];
            }
            #pragma unroll
            for (int mi = 0; mi < 2; mi++)
                #pragma unroll
                for (int ni = 0; ni < 4; ni++)
                    mma_tf32(acc[mi][ni], af[mi], bf[ni]);
        }
    };

    int nk = (K + BKT - 1) / BKT;
    loadTile(0);
    storeTile(0, 0);
    __syncthreads();
    int buf = 0;
    for (int i = 0; i < nk; i++) {
        if (i + 1 < nk) loadTile((i + 1) * BKT);
        compute(buf);
        if (i + 1 < nk) {
            storeTile(buf ^ 1, (i + 1) * BKT);
            buf ^= 1;
            __syncthreads();
        }
    }

    #pragma unroll
    for (int mi = 0; mi < 2; mi++) {
        #pragma unroll
        for (int ni = 0; ni < 4; ni++) {
            #pragma unroll
            for (int half = 0; half < 2; half++) {
                int r = m0 + mW + mi * 16 + g + half * 8;
                if (r >= M) continue;
                int c = n0 + nW + ni * 8 + tg * 2;
                float v0 = acc[mi][ni][half * 2];
                float v1 = acc[mi][ni][half * 2 + 1];
                if (c + 2 <= N) {
                    float2 w; w.x = v0; w.y = v1;
                    *(float2*)(Cb + (long long)r * rsC + c) = w;
                } else {
                    if (c < N)     Cb[(long long)r * rsC + c] = v0;
                    if (c + 1 < N) Cb[(long long)r * rsC + c + 1] = v1;
                }
            }
        }
    }
}

// ============ tgemm128: tile 128x128, BK=16 (projections, csB=1) =============
#define BNT2 128
#define PP  136
__global__ __launch_bounds__(256) void tgemm128(int M, int N, int K,
    const float* __restrict__ A, long long rsA, long long csA,
    const float* __restrict__ B, long long rsB, long long csB,
    float* __restrict__ C, long long rsC, long long csC,
    const float* __restrict__ Bi, long long rsBi, long long csBi,
    float alpha)
{
    __shared__ uint32_t As[2][BKT][PP];
    __shared__ uint32_t Bs[2][BKT][PP];

    const float* Ab = A;
    const float* Bb = B;
    float*       Cb = C;
    const float* Bib = Bi;

    int m0 = blockIdx.y * BMT;
    int n0 = blockIdx.x * BNT2;
    int tid  = threadIdx.x;
    int warp = tid >> 5;
    int lane = tid & 31;
    int g  = lane >> 2;
    int tg = lane & 3;
    int wm = warp & 1;
    int wn = warp >> 1;
    int mW = wm * 64;
    int nW = wn * 32;

    int amM = tid & 127;
    int akq = tid >> 7;
    const bool bContigN = (csB == 1);

    float acc[4][4][4];
    #pragma unroll
    for (int i = 0; i < 4; i++)
        #pragma unroll
        for (int j = 0; j < 4; j++)
            #pragma unroll
            for (int l = 0; l < 4; l++) acc[i][j][l] = 0.f;

    float4 va[2], vb[2];

    auto loadTile = [&](int k0) {
        #pragma unroll
        for (int i = 0; i < 2; i++) {
            int kq = akq + i * 2;
            int gm = m0 + amM, gk = k0 + kq * 4;
            float4 v = make_float4(0.f, 0.f, 0.f, 0.f);
            if (gm < M) {
                if (csA == 1 && gk + 4 <= K) {
                    v = *(const float4*)(Ab + (long long)gm * rsA + gk);
                } else {
                    float* pv = (float*)&v;
                    #pragma unroll
                    for (int j = 0; j < 4; j++)
                        if (gk + j < K) pv[j] = Ab[(long long)gm * rsA + (long long)(gk + j) * csA];
                }
            }
            va[i] = v;
        }
        #pragma unroll
        for (int i = 0; i < 2; i++) {
            int slot = tid + i * 256;
            float4 v = make_float4(0.f, 0.f, 0.f, 0.f);
            if (bContigN) {
                int kk = slot >> 5, nq = slot & 31;
                int gk = k0 + kk, gn = n0 + nq * 4;
                if (gk < K) {
                    if (gn + 4 <= N) {
                        v = *(const float4*)(Bb + (long long)gk * rsB + gn);
                    } else {
                        float* pv = (float*)&v;
                        #pragma unroll
                        for (int j = 0; j < 4; j++)
                            if (gn + j < N) pv[j] = Bb[(long long)gk * rsB + (long long)(gn + j)];
                    }
                }
            } else {
                int nn = slot >> 2, kq2 = slot & 3;
                int gn = n0 + nn, gk = k0 + kq2 * 4;
                if (gn < N) {
                    if (rsB == 1 && gk + 4 <= K) {
                        v = *(const float4*)(Bb + (long long)gn * csB + gk);
                    } else {
                        float* pv = (float*)&v;
                        #pragma unroll
                        for (int j = 0; j < 4; j++)
                            if (gk + j < K) pv[j] = Bb[(long long)(gk + j) * rsB + (long long)gn * csB];
                    }
                }
            }
            vb[i] = v;
        }
    };

    auto storeTile = [&](int bsel) {
        #pragma unroll
        for (int i = 0; i < 2; i++) {
            int kq = akq + i * 2;
            const float* pv = (const float*)&va[i];
            #pragma unroll
            for (int j = 0; j < 4; j++)
                As[bsel][kq * 4 + j][amM] = f2tf32(pv[j]);
        }
        #pragma unroll
        for (int i = 0; i < 2; i++) {
            int slot = tid + i * 256;
            const float* pv = (const float*)&vb[i];
            if (bContigN) {
                int kk = slot >> 5, nq = slot & 31;
                uint4 u;
                u.x = f2tf32(pv[0]); u.y = f2tf32(pv[1]);
                u.z = f2tf32(pv[2]); u.w = f2tf32(pv[3]);
                *(uint4*)&Bs[bsel][kk][nq * 4] = u;
            } else {
                int nn = slot >> 2, kq2 = slot & 3;
                #pragma unroll
                for (int j = 0; j < 4; j++)
                    Bs[bsel][kq2 * 4 + j][nn] = f2tf32(pv[j]);
            }
        }
    };

    auto compute = [&](int bsel) {
        #pragma unroll
        for (int ks = 0; ks < 2; ks++) {
            int kk = ks * 8;
            uint32_t af[4][4];
            #pragma unroll
            for (int mi = 0; mi < 4; mi++) {
                int mb = mW + mi * 16;
                af[mi][0] = As[bsel][kk + tg][mb + g];
                af[mi][1] = As[bsel][kk + tg][mb + g + 8];
                af[mi][2] = As[bsel][kk + tg + 4][mb + g];
                af[mi][3] = As[bsel][kk + tg + 4][mb + g + 8];
            }
            uint32_t bf[4][2];
            #pragma unroll
            for (int ni = 0; ni < 4; ni++) {
                int nb = nW + ni * 8;
                bf[ni][0] = Bs[bsel][kk + tg][nb + g];
                bf[ni][1] = Bs[bsel][kk + tg + 4][nb + g];
            }
            #pragma unroll
            for (int mi = 0; mi < 4; mi++)
                #pragma unroll
                for (int ni = 0; ni < 4; ni++)
                    mma_tf32(acc[mi][ni], af[mi], bf[ni]);
        }
    };

    int nk = (K + BKT - 1) / BKT;
    loadTile(0);
    storeTile(0);
    __syncthreads();
    int buf = 0;
    for (int i = 0; i < nk; i++) {
        if (i + 1 < nk) loadTile((i + 1) * BKT);
        compute(buf);
        if (i + 1 < nk) {
            storeTile(buf ^ 1);
            buf ^= 1;
            __syncthreads();
        }
    }

    bool vecC = (csC == 1) && ((rsC & 1) == 0);
    #pragma unroll
    for (int mi = 0; mi < 4; mi++) {
        #pragma unroll
        for (int ni = 0; ni < 4; ni++) {
            #pragma unroll
            for (int half = 0; half < 2; half++) {
                int r = m0 + mW + mi * 16 + g + half * 8;
                if (r >= M) continue;
                int c = n0 + nW + ni * 8 + tg * 2;
                float v0 = alpha * acc[mi][ni][half * 2];
                float v1 = alpha * acc[mi][ni][half * 2 + 1];
                if (Bib) {
                    if (c < N)     v0 += Bib[(long long)r * rsBi + (long long)c * csBi];
                    if (c + 1 < N) v1 += Bib[(long long)r * rsBi + (long long)(c + 1) * csBi];
                }
                if (vecC && c + 2 <= N) {
                    float2 w; w.x = v0; w.y = v1;
                    *(float2*)(Cb + (long long)r * rsC + c) = w;
                } else {
                    if (c < N)     Cb[(long long)r * rsC + (long long)c * csC] = v0;
                    if (c + 1 < N) Cb[(long long)r * rsC + (long long)(c + 1) * csC] = v1;
                }
            }
        }
    }
}

// ---------------- pooling ----------------------------------------------------
__global__ void pool_kernel(const float* __restrict__ q, float* __restrict__ adla)
{
    long long t = (long long)blockIdx.x * blockDim.x + threadIdx.x;
    if (t >= (long long)BATCH * ADLAV * DIMV) return;
    int c = (int)(t % DIMV);
    int a = (int)((t / DIMV) % ADLAV);
    int b = (int)(t / ((long long)DIMV * ADLAV));
    int p0 = a / 49, p1 = (a / 7) % 7, p2 = a % 7;
    float s = 0.f;
    #pragma unroll
    for (int r0 = 0; r0 < 2; r0++)
        #pragma unroll
        for (int r1 = 0; r1 < 2; r1++)
            #pragma unroll
            for (int r2 = 0; r2 < 2; r2++) {
                int i = p0 * 2 + r0, j = p1 * 2 + r1, k = p2 * 2 + r2;
                int n = (i * HWD + j) * HWD + k;
                s += q[((long long)b * NTOK + n) * DIMV + c];
            }
    adla[t] = s * 0.125f;
}

// ---------------- trilinear weights (7 -> 14) --------------------------------
__device__ __forceinline__ void lin_w(int o, int& x0, int& x1, float& w)
{
    float x = 0.5f * (float)o - 0.25f;
    x = fminf(fmaxf(x, 0.f), 6.f);
    x0 = (int)floorf(x);
    if (x0 > 6) x0 = 6;
    x1 = min(x0 + 1, 6);
    w = x - (float)x0;
}

__global__ void biasprep(const float* __restrict__ an, const float* __restrict__ na,
                         const float* __restrict__ ah, const float* __restrict__ aw,
                         const float* __restrict__ ad, const float* __restrict__ ha,
                         const float* __restrict__ wa, const float* __restrict__ da,
                         float* __restrict__ b1, float* __restrict__ b2)
{
    int haid = blockIdx.x;
    int h = haid / ADLAV;
    int a = haid % ADLAV;
    __shared__ float s_an[343], s_na[343];
    __shared__ float s_ax[3][14];
    __shared__ float s_xa[3][14];
    int tid = threadIdx.x;
    const float* anb = an + (long long)haid * 343;
    const float* nab = na + (long long)haid * 343;
    for (int i = tid; i < 343; i += 256) { s_an[i] = anb[i]; s_na[i] = nab[i]; }
    if (tid < 14) {
        s_ax[0][tid] = ah[(long long)haid * HWD + tid];
        s_ax[1][tid] = aw[(long long)haid * HWD + tid];
        s_ax[2][tid] = ad[(long long)haid * HWD + tid];
        s_xa[0][tid] = ha[((long long)h * HWD + tid) * ADLAV + a];
        s_xa[1][tid] = wa[((long long)h * HWD + tid) * ADLAV + a];
        s_xa[2][tid] = da[((long long)h * HWD + tid) * ADLAV + a];
    }
    __syncthreads();
    long long base = (long long)haid * NTOK;
    for (int n = tid; n < NTOK; n += 256) {
        int i = n / (HWD * HWD), j = (n / HWD) % HWD, k = n % HWD;
        int i0, i1, j0, j1, k0, k1;
        float wi, wj, wk;
        lin_w(i, i0, i1, wi);
        lin_w(j, j0, j1, wj);
        lin_w(k, k0, k1, wk);
        float v1, v2;
        {
            const float* t = s_an;
            float c00 = (1.f-wk)*t[(i0*7+j0)*7+k0] + wk*t[(i0*7+j0)*7+k1];
            float c01 = (1.f-wk)*t[(i0*7+j1)*7+k0] + wk*t[(i0*7+j1)*7+k1];
            float c10 = (1.f-wk)*t[(i1*7+j0)*7+k0] + wk*t[(i1*7+j0)*7+k1];
            float c11 = (1.f-wk)*t[(i1*7+j1)*7+k0] + wk*t[(i1*7+j1)*7+k1];
            v1 = (1.f-wi)*((1.f-wj)*c00 + wj*c01) + wi*((1.f-wj)*c10 + wj*c11);
        }
        {
            const float* t = s_na;
            float c00 = (1.f-wk)*t[(i0*7+j0)*7+k0] + wk*t[(i0*7+j0)*7+k1];
            float c01 = (1.f-wk)*t[(i0*7+j1)*7+k0] + wk*t[(i0*7+j1)*7+k1];
            float c10 = (1.f-wk)*t[(i1*7+j0)*7+k0] + wk*t[(i1*7+j0)*7+k1];
            float c11 = (1.f-wk)*t[(i1*7+j1)*7+k0] + wk*t[(i1*7+j1)*7+k1];
            v2 = (1.f-wi)*((1.f-wj)*c00 + wj*c01) + wi*((1.f-wj)*c10 + wj*c11);
        }
        v1 += s_ax[0][i] + s_ax[1][j] + s_ax[2][k];
        v2 += s_xa[0][i] + s_xa[1][j] + s_xa[2][k];
        b1[base + n] = v1;
        b2[base + n] = v2;
    }
}

// tiled transpose: b2[h,a,n] -> b2t[h,n,a]
__global__ void transpose_b2(const float* __restrict__ b2, float* __restrict__ b2t)
{
    __shared__ float t[32][33];
    int h = blockIdx.z;
    int a0 = blockIdx.y * 32, n0 = blockIdx.x * 32;
    int x = threadIdx.x, y = threadIdx.y;
    #pragma unroll
    for (int yy = y; yy < 32; yy += 8) {
        int a = a0 + yy, n = n0 + x;
        if (a < ADLAV && n < NTOK)
            t[yy][x] = b2[((long long)h * ADLAV + a) * NTOK + n];
    }
    __syncthreads();
    #pragma unroll
    for (int yy = y; yy < 32; yy += 8) {
        int n = n0 + yy, a = a0 + x;
        if (a < ADLAV && n < NTOK)
            b2t[((long long)h * NTOK + n) * ADLAV + a] = t[x][yy];
    }
}

// ---------------- depthwise 3x3x3 conv (SAME), add into out ------------------
__global__ void dwc_add(const float* __restrict__ kv, const float* __restrict__ w,
                        const float* __restrict__ bvec, float* __restrict__ out)
{
    long long t = (long long)blockIdx.x * blockDim.x + threadIdx.x;
    if (t >= (long long)BATCH * NTOK * DIMV) return;
    int c = (int)(t % DIMV);
    int n = (int)((t / DIMV) % NTOK);
    int b = (int)(t / ((long long)DIMV * NTOK));
    int i = n / (HWD * HWD), j = (n / HWD) % HWD, k = n % HWD;
    float acc = bvec[c];
    const float* wc = w + (long long)c * 27;
    #pragma unroll
    for (int di = -1; di <= 1; di++) {
        int ii = i + di;
        if (ii < 0 || ii >= HWD) continue;
        #pragma unroll
        for (int dj = -1; dj <= 1; dj++) {
            int jj = j + dj;
            if (jj < 0 || jj >= HWD) continue;
            #pragma unroll
            for (int dk = -1; dk <= 1; dk++) {
                int kk = k + dk;
                if (kk < 0 || kk >= HWD) continue;
                int nn = (ii * HWD + jj) * HWD + kk;
                acc += kv[((long long)b * NTOK + nn) * (2 * DIMV) + DIMV + c]
                     * wc[(di + 1) * 9 + (dj + 1) * 3 + (dk + 1)];
            }
        }
    }
    out[t] += acc;
}

// ---------------- host launcher ----------------------------------------------
static inline dim3 gT64(int M, int N, int Z) {
    return dim3((unsigned)((N + BNT - 1) / BNT), (unsigned)((M + BMT - 1) / BMT), (unsigned)Z);
}
static inline dim3 gT128(int M, int N) {
    return dim3((unsigned)((N + BNT2 - 1) / BNT2), (unsigned)((M + BMT - 1) / BMT), 1);
}

extern "C" void kernel_launch(void* const* d_in, const int* in_sizes, int n_in,
                              void* d_out, int out_size)
{
    const float* x     = (const float*)d_in[0];
    const float* Wq    = (const float*)d_in[1];
    const float* Wkv   = (const float*)d_in[2];
    const float* Wproj = (const float*)d_in[3];
    const float* bproj = (const float*)d_in[4];
    const float* dwcw  = (const float*)d_in[5];
    const float* dwcb  = (const float*)d_in[6];
    const float* an    = (const float*)d_in[7];
    const float* na    = (const float*)d_in[8];
    const float* ah    = (const float*)d_in[9];
    const float* aw    = (const float*)d_in[10];
    const float* ad    = (const float*)d_in[11];
    const float* ha    = (const float*)d_in[12];
    const float* wa    = (const float*)d_in[13];
    const float* da    = (const float*)d_in[14];
    float* out = (float*)d_out;

    void *pq, *pkv, *padla, *pb1, *pb2, *pb2t, *plog, *pav, *pao;
    cudaGetSymbolAddress(&pq, g_q);
    cudaGetSymbolAddress(&pkv, g_kv);
    cudaGetSymbolAddress(&padla, g_adla);
    cudaGetSymbolAddress(&pb1, g_bias1);
    cudaGetSymbolAddress(&pb2, g_bias2);
    cudaGetSymbolAddress(&pb2t, g_bias2t);
    cudaGetSymbolAddress(&plog, g_logits);
    cudaGetSymbolAddress(&pav, g_adlav);
    cudaGetSymbolAddress(&pao, g_attnout);
    float* q    = (float*)pq;
    float* kv   = (float*)pkv;
    float* adla = (float*)padla;
    float* b1   = (float*)pb1;
    float* b2   = (float*)pb2;
    float* b2t  = (float*)pb2t;
    float* lg   = (float*)plog;
    float* av   = (float*)pav;
    float* ao   = (float*)pao;

    // 1. q = x @ Wq
    tgemm128<<<gT128(BN_TOT, DIMV), 256>>>(BN_TOT, DIMV, DIMV,
        x,  DIMV, 1,
        Wq, DIMV, 1,
        q,  DIMV, 1,
        nullptr, 0, 0, 1.f);

    // 2. kv = x @ Wkv
    tgemm128<<<gT128(BN_TOT, 2 * DIMV), 256>>>(BN_TOT, 2 * DIMV, DIMV,
        x,   DIMV,    1,
        Wkv, 2 * DIMV, 1,
        kv,  2 * DIMV, 1,
        nullptr, 0, 0, 1.f);

    // 3. adla pooling
    {
        long long tot = (long long)BATCH * ADLAV * DIMV;
        pool_kernel<<<(unsigned)((tot + 255) / 256), 256>>>(q, adla);
    }

    // 4. bias tables + transpose
    biasprep<<<HEADS * ADLAV, 256>>>(an, na, ah, aw, ad, ha, wa, da, b1, b2);
    transpose_b2<<<dim3((NTOK + 31) / 32, (ADLAV + 31) / 32, HEADS), dim3(32, 8)>>>(b2, b2t);

    // 5. attn1 logits (z head-major for bias L2 reuse: b-slot=head, h-slot=batch)
    tgemm64<<<gT64(ADLAV, NTOK, BATCH * HEADS), 256>>>(ADLAV, NTOK, HD,
        adla, DIMV, 1, HD, (long long)ADLAV * DIMV,
        kv,   1, 2 * DIMV, HD, (long long)NTOK * 2 * DIMV,
        lg,   NTOK, 1, (long long)ADLAV * NTOK, (long long)HEADS * ADLAV * NTOK,
        b1,   NTOK, 1, (long long)ADLAV * NTOK, 0,
        SCALEV);

    // 6. adla_v = softmax(lg) @ V — fused (z standard: b-slot=batch, h-slot=head)
    pv_fused<<<gT64(ADLAV, HD, BATCH * HEADS), 256>>>(ADLAV, HD, NTOK,
        lg,        NTOK, (long long)HEADS * ADLAV * NTOK, (long long)ADLAV * NTOK,
        kv + DIMV, 2 * DIMV, (long long)NTOK * 2 * DIMV, HD,
        av,        HD, (long long)HEADS * ADLAV * HD, (long long)ADLAV * HD);

    // 7. attn2 logits (z head-major, padded rows)
    tgemm64<<<gT64(NTOK, ADLAV, BATCH * HEADS), 256>>>(NTOK, ADLAV, HD,
        q,    DIMV, 1, HD, (long long)NTOK * DIMV,
        adla, 1, DIMV, HD, (long long)ADLAV * DIMV,
        lg,   LG2PAD, 1, (long long)NTOK * LG2PAD, (long long)HEADS * NTOK * LG2PAD,
        b2t,  ADLAV, 1, (long long)NTOK * ADLAV, 0,
        SCALEV);

    // 8. attnout = softmax(lg) @ adla_v — fused
    pv_fused<<<gT64(NTOK, HD, BATCH * HEADS), 256>>>(NTOK, HD, ADLAV,
        lg, LG2PAD, (long long)HEADS * NTOK * LG2PAD, (long long)NTOK * LG2PAD,
        av, HD, (long long)HEADS * ADLAV * HD, (long long)ADLAV * HD,
        ao, DIMV, (long long)NTOK * DIMV, HD);

    // 9. depthwise conv 3x3x3 of v, added into attnout
    {
        long long tot = (long long)BATCH * NTOK * DIMV;
        dwc_add<<<(unsigned)((tot + 255) / 256), 256>>>(kv, dwcw, dwcb, ao);
    }

    // 10. final: out = attnout @ Wproj + bproj
    tgemm128<<<gT128(BN_TOT, DIMV), 256>>>(BN_TOT, DIMV, DIMV,
        ao,    DIMV, 1,
        Wproj, DIMV, 1,
        out,   DIMV, 1,
        bproj, 0, 1,
        1.f);

    (void)in_sizes; (void)n_in; (void)out_size;
}

// round 11
// speedup vs baseline: 1.1322x; 1.1322x over previous
#include <cuda_runtime.h>
#include <math.h>
#include <stdint.h>

#define HEADS   8
#define DIMV    384
#define HD      48
#define ADLAV   343
#define HWD     14
#define NTOK    2744
#define BATCH   8
#define SCALEV  0.14433756729740645f   // 48^-0.5
#define LG2PAD  352                    // padded row stride for attn2 logits

#define BN_TOT  (BATCH * NTOK)         // 21952

// ---------------- scratch (static device allocations) ------------------------
__device__ float g_q[BATCH * NTOK * DIMV];
__device__ float g_kv[BATCH * NTOK * 2 * DIMV];
__device__ float g_adla[BATCH * ADLAV * DIMV];
__device__ float g_bias1[HEADS * ADLAV * NTOK];
__device__ float g_bias2[HEADS * ADLAV * NTOK];      // [h,a,n]
__device__ float g_bias2t[HEADS * ADLAV * NTOK];     // [h,n,a]
__device__ float g_logits[BATCH * HEADS * NTOK * LG2PAD];  // raw logits, reused
__device__ float g_adlav[BATCH * HEADS * ADLAV * HD];
__device__ float g_attnout[BATCH * NTOK * DIMV];

// ---------------- tf32 helpers ----------------------------------------------
__device__ __forceinline__ uint32_t f2tf32(float x) {
    uint32_t r;
    asm("cvt.rna.tf32.f32 %0, %1;" : "=r"(r) : "f"(x));
    return r;
}

__device__ __forceinline__ void mma_tf32(float* c, const uint32_t* a, const uint32_t* b) {
    asm volatile(
        "mma.sync.aligned.m16n8k8.row.col.f32.tf32.tf32.f32 "
        "{%0,%1,%2,%3}, {%4,%5,%6,%7}, {%8,%9}, {%0,%1,%2,%3};\n"
        : "+f"(c[0]), "+f"(c[1]), "+f"(c[2]), "+f"(c[3])
        : "r"(a[0]), "r"(a[1]), "r"(a[2]), "r"(a[3]), "r"(b[0]), "r"(b[1]));
}

// ============ tgemm64: tile 128x64, BK=16 (R5/R8-proven, batched cases) ======
#define BMT 128
#define BNT 64
#define BKT 16
#define PA 136
#define PB 72
__global__ __launch_bounds__(256) void tgemm64(int M, int N, int K,
    const float* __restrict__ A, long long rsA, long long csA, long long bAb, long long bAh,
    const float* __restrict__ B, long long rsB, long long csB, long long bBb, long long bBh,
    float* __restrict__ C, long long rsC, long long csC, long long bCb, long long bCh,
    const float* __restrict__ Bi, long long rsBi, long long csBi, long long bBih,
    float alpha)
{
    __shared__ uint32_t As[2][BKT][PA];
    __shared__ uint32_t Bs[2][BKT][PB];

    int z  = blockIdx.z;
    int bb = z >> 3;
    int hh = z & 7;
    const float* Ab = A + (long long)bb * bAb + (long long)hh * bAh;
    const float* Bb = B + (long long)bb * bBb + (long long)hh * bBh;
    float*       Cb = C + (long long)bb * bCb + (long long)hh * bCh;
    const float* Bib = Bi ? (Bi + (long long)hh * bBih) : nullptr;

    int m0 = blockIdx.y * BMT;
    int n0 = blockIdx.x * BNT;
    int tid  = threadIdx.x;
    int warp = tid >> 5;
    int lane = tid & 31;
    int g  = lane >> 2;
    int tg = lane & 3;
    int wm = warp & 3;
    int wn = warp >> 2;
    int mW = wm * 32;
    int nW = wn * 32;

    int amM = tid & 127;
    int akq = tid >> 7;
    int bnKK = tid >> 4;
    int bnNQ = tid & 15;
    int bkN  = tid & 63;
    int bkKQ = tid >> 6;
    const bool bContigN = (csB == 1);

    float acc[2][4][4];
    #pragma unroll
    for (int i = 0; i < 2; i++)
        #pragma unroll
        for (int j = 0; j < 4; j++)
            #pragma unroll
            for (int l = 0; l < 4; l++) acc[i][j][l] = 0.f;

    float4 va[2], vb;

    auto loadTile = [&](int k0) {
        #pragma unroll
        for (int i = 0; i < 2; i++) {
            int kq = akq + i * 2;
            int gm = m0 + amM, gk = k0 + kq * 4;
            float4 v = make_float4(0.f, 0.f, 0.f, 0.f);
            if (gm < M) {
                if (csA == 1 && gk + 4 <= K) {
                    v = *(const float4*)(Ab + (long long)gm * rsA + gk);
                } else {
                    float* pv = (float*)&v;
                    #pragma unroll
                    for (int j = 0; j < 4; j++)
                        if (gk + j < K) pv[j] = Ab[(long long)gm * rsA + (long long)(gk + j) * csA];
                }
            }
            va[i] = v;
        }
        float4 v = make_float4(0.f, 0.f, 0.f, 0.f);
        if (bContigN) {
            int gk = k0 + bnKK, gn = n0 + bnNQ * 4;
            if (gk < K) {
                if (gn + 4 <= N) {
                    v = *(const float4*)(Bb + (long long)gk * rsB + gn);
                } else {
                    float* pv = (float*)&v;
                    #pragma unroll
                    for (int j = 0; j < 4; j++)
                        if (gn + j < N) pv[j] = Bb[(long long)gk * rsB + (long long)(gn + j)];
                }
            }
        } else {
            int gn = n0 + bkN, gk = k0 + bkKQ * 4;
            if (gn < N) {
                if (rsB == 1 && gk + 4 <= K) {
                    v = *(const float4*)(Bb + (long long)gn * csB + gk);
                } else {
                    float* pv = (float*)&v;
                    #pragma unroll
                    for (int j = 0; j < 4; j++)
                        if (gk + j < K) pv[j] = Bb[(long long)(gk + j) * rsB + (long long)gn * csB];
                }
            }
        }
        vb = v;
    };

    auto storeTile = [&](int bsel) {
        #pragma unroll
        for (int i = 0; i < 2; i++) {
            int kq = akq + i * 2;
            const float* pv = (const float*)&va[i];
            #pragma unroll
            for (int j = 0; j < 4; j++)
                As[bsel][kq * 4 + j][amM] = f2tf32(pv[j]);
        }
        const float* pv = (const float*)&vb;
        if (bContigN) {
            uint4 u;
            u.x = f2tf32(pv[0]); u.y = f2tf32(pv[1]);
            u.z = f2tf32(pv[2]); u.w = f2tf32(pv[3]);
            *(uint4*)&Bs[bsel][bnKK][bnNQ * 4] = u;
        } else {
            #pragma unroll
            for (int j = 0; j < 4; j++)
                Bs[bsel][bkKQ * 4 + j][bkN] = f2tf32(pv[j]);
        }
    };

    auto compute = [&](int bsel) {
        #pragma unroll
        for (int ks = 0; ks < 2; ks++) {
            int kk = ks * 8;
            uint32_t af[2][4];
            #pragma unroll
            for (int mi = 0; mi < 2; mi++) {
                int mb = mW + mi * 16;
                af[mi][0] = As[bsel][kk + tg][mb + g];
                af[mi][1] = As[bsel][kk + tg][mb + g + 8];
                af[mi][2] = As[bsel][kk + tg + 4][mb + g];
                af[mi][3] = As[bsel][kk + tg + 4][mb + g + 8];
            }
            uint32_t bf[4][2];
            #pragma unroll
            for (int ni = 0; ni < 4; ni++) {
                int nb = nW + ni * 8;
                bf[ni][0] = Bs[bsel][kk + tg][nb + g];
                bf[ni][1] = Bs[bsel][kk + tg + 4][nb + g];
            }
            #pragma unroll
            for (int mi = 0; mi < 2; mi++)
                #pragma unroll
                for (int ni = 0; ni < 4; ni++)
                    mma_tf32(acc[mi][ni], af[mi], bf[ni]);
        }
    };

    int nk = (K + BKT - 1) / BKT;
    loadTile(0);
    storeTile(0);
    __syncthreads();
    int buf = 0;
    for (int i = 0; i < nk; i++) {
        if (i + 1 < nk) loadTile((i + 1) * BKT);
        compute(buf);
        if (i + 1 < nk) {
            storeTile(buf ^ 1);
            buf ^= 1;
            __syncthreads();
        }
    }

    bool vecC = (csC == 1) && ((rsC & 1) == 0);
    #pragma unroll
    for (int mi = 0; mi < 2; mi++) {
        #pragma unroll
        for (int ni = 0; ni < 4; ni++) {
            #pragma unroll
            for (int half = 0; half < 2; half++) {
                int r = m0 + mW + mi * 16 + g + half * 8;
                if (r >= M) continue;
                int c = n0 + nW + ni * 8 + tg * 2;
                float v0 = alpha * acc[mi][ni][half * 2];
                float v1 = alpha * acc[mi][ni][half * 2 + 1];
                if (Bib) {
                    if (c < N)     v0 += Bib[(long long)r * rsBi + (long long)c * csBi];
                    if (c + 1 < N) v1 += Bib[(long long)r * rsBi + (long long)(c + 1) * csBi];
                }
                if (vecC && c + 2 <= N) {
                    float2 w; w.x = v0; w.y = v1;
                    *(float2*)(Cb + (long long)r * rsC + c) = w;
                } else {
                    if (c < N)     Cb[(long long)r * rsC + (long long)c * csC] = v0;
                    if (c + 1 < N) Cb[(long long)r * rsC + (long long)(c + 1) * csC] = v1;
                }
            }
        }
    }
}

// ============ pv_exp: single-pass softmax(s) @ V =============================
// A = raw logits (csA=1, bounded magnitude -> exp without max subtraction).
// p~ = exp(s) computed in the A smem fill; row sums obtained for free by a
// ones-column planted at B column N (N=48 < 64-wide tile); epilogue divides.
// Requires: N even, N+1 <= BNT, csB = 1.
__global__ __launch_bounds__(256) void pv_exp(int M, int N, int K,
    const float* __restrict__ A, int rsA, long long bAb, long long bAh,
    const float* __restrict__ B, int rsB, long long bBb, long long bBh,
    float* __restrict__ C, int rsC, long long bCb, long long bCh)
{
    __shared__ uint32_t As[2][BKT][PA];
    __shared__ uint32_t Bs[2][BKT][PB];
    __shared__ float sSum[BMT];

    int z  = blockIdx.z;
    int bb = z >> 3;
    int hh = z & 7;
    const float* Ab = A + (long long)bb * bAb + (long long)hh * bAh;
    const float* Bb = B + (long long)bb * bBb + (long long)hh * bBh;
    float*       Cb = C + (long long)bb * bCb + (long long)hh * bCh;

    int m0 = blockIdx.y * BMT;
    int tid  = threadIdx.x;
    int warp = tid >> 5;
    int lane = tid & 31;
    int g  = lane >> 2;
    int tg = lane & 3;
    int wm = warp & 3;
    int wn = warp >> 2;
    int mW = wm * 32;
    int nW = wn * 32;

    int amM = tid & 127;
    int akq = tid >> 7;
    int bnKK = tid >> 4;
    int bnNQ = tid & 15;
    bool rowOk = (m0 + amM) < M;

    float acc[2][4][4];
    #pragma unroll
    for (int i = 0; i < 2; i++)
        #pragma unroll
        for (int j = 0; j < 4; j++)
            #pragma unroll
            for (int l = 0; l < 4; l++) acc[i][j][l] = 0.f;

    float4 va[2], vb;

    auto loadTile = [&](int k0) {
        #pragma unroll
        for (int i = 0; i < 2; i++) {
            int kq = akq + i * 2;
            int gm = m0 + amM, gk = k0 + kq * 4;
            float4 v = make_float4(0.f, 0.f, 0.f, 0.f);
            if (gm < M) {
                if (gk + 4 <= K) {
                    v = *(const float4*)(Ab + (long long)gm * rsA + gk);
                } else {
                    float* pv = (float*)&v;
                    #pragma unroll
                    for (int j = 0; j < 4; j++)
                        if (gk + j < K) pv[j] = Ab[(long long)gm * rsA + gk + j];
                }
            }
            va[i] = v;
        }
        float4 v = make_float4(0.f, 0.f, 0.f, 0.f);
        int gk = k0 + bnKK, gn = bnNQ * 4;
        if (gk < K) {
            if (gn + 4 <= N) {
                v = *(const float4*)(Bb + (long long)gk * rsB + gn);
            } else {
                float* pv = (float*)&v;
                #pragma unroll
                for (int j = 0; j < 4; j++)
                    if (gn + j < N) pv[j] = Bb[(long long)gk * rsB + (long long)(gn + j)];
                if (gn == N) pv[0] = 1.0f;     // ones column -> row sums
            }
        }
        vb = v;
    };

    auto storeTile = [&](int bsel, int k0) {
        #pragma unroll
        for (int i = 0; i < 2; i++) {
            int kq = akq + i * 2;
            int gk = k0 + kq * 4;
            const float* pv = (const float*)&va[i];
            #pragma unroll
            for (int j = 0; j < 4; j++) {
                uint32_t u = 0u;
                if (rowOk && gk + j < K) u = f2tf32(__expf(pv[j]));
                As[bsel][kq * 4 + j][amM] = u;
            }
        }
        const float* pv = (const float*)&vb;
        uint4 u;
        u.x = f2tf32(pv[0]); u.y = f2tf32(pv[1]);
        u.z = f2tf32(pv[2]); u.w = f2tf32(pv[3]);
        *(uint4*)&Bs[bsel][bnKK][bnNQ * 4] = u;
    };

    auto compute = [&](int bsel) {
        #pragma unroll
        for (int ks = 0; ks < 2; ks++) {
            int kk = ks * 8;
            uint32_t af[2][4];
            #pragma unroll
            for (int mi = 0; mi < 2; mi++) {
                int mb = mW + mi * 16;
                af[mi][0] = As[bsel][kk + tg][mb + g];
                af[mi][1] = As[bsel][kk + tg][mb + g + 8];
                af[mi][2] = As[bsel][kk + tg + 4][mb + g];
                af[mi][3] = As[bsel][kk + tg + 4][mb + g + 8];
            }
            uint32_t bf[4][2];
            #pragma unroll
            for (int ni = 0; ni < 4; ni++) {
                int nb = nW + ni * 8;
                bf[ni][0] = Bs[bsel][kk + tg][nb + g];
                bf[ni][1] = Bs[bsel][kk + tg + 4][nb + g];
            }
            #pragma unroll
            for (int mi = 0; mi < 2; mi++)
                #pragma unroll
                for (int ni = 0; ni < 4; ni++)
                    mma_tf32(acc[mi][ni], af[mi], bf[ni]);
        }
    };

    int nk = (K + BKT - 1) / BKT;
    loadTile(0);
    storeTile(0, 0);
    __syncthreads();
    int buf = 0;
    for (int i = 0; i < nk; i++) {
        if (i + 1 < nk) loadTile((i + 1) * BKT);
        compute(buf);
        if (i + 1 < nk) {
            storeTile(buf ^ 1, (i + 1) * BKT);
            buf ^= 1;
            __syncthreads();
        }
    }

    // ---- extract row sums (accumulator column == N) ----
    #pragma unroll
    for (int mi = 0; mi < 2; mi++) {
        #pragma unroll
        for (int ni = 0; ni < 4; ni++) {
            int c = nW + ni * 8 + tg * 2;
            if (c == N) {
                #pragma unroll
                for (int half = 0; half < 2; half++) {
                    int rr = mW + mi * 16 + g + half * 8;
                    sSum[rr] = acc[mi][ni][half * 2];
                }
            }
        }
    }
    __syncthreads();

    // ---- normalize + store ----
    #pragma unroll
    for (int mi = 0; mi < 2; mi++) {
        #pragma unroll
        for (int ni = 0; ni < 4; ni++) {
            #pragma unroll
            for (int half = 0; half < 2; half++) {
                int rr = mW + mi * 16 + g + half * 8;
                int r = m0 + rr;
                if (r >= M) continue;
                int c = nW + ni * 8 + tg * 2;
                if (c >= N) continue;
                float inv = 1.f / sSum[rr];
                float2 w;
                w.x = acc[mi][ni][half * 2] * inv;
                w.y = acc[mi][ni][half * 2 + 1] * inv;
                *(float2*)(Cb + (long long)r * rsC + c) = w;
            }
        }
    }
}

// ============ tgemm128: tile 128x128, BK=16 (projections, csB=1) =============
#define BNT2 128
#define PP  136
__global__ __launch_bounds__(256) void tgemm128(int M, int N, int K,
    const float* __restrict__ A, long long rsA, long long csA,
    const float* __restrict__ B, long long rsB, long long csB,
    float* __restrict__ C, long long rsC, long long csC,
    const float* __restrict__ Bi, long long rsBi, long long csBi,
    float alpha)
{
    __shared__ uint32_t As[2][BKT][PP];
    __shared__ uint32_t Bs[2][BKT][PP];

    const float* Ab = A;
    const float* Bb = B;
    float*       Cb = C;
    const float* Bib = Bi;

    int m0 = blockIdx.y * BMT;
    int n0 = blockIdx.x * BNT2;
    int tid  = threadIdx.x;
    int warp = tid >> 5;
    int lane = tid & 31;
    int g  = lane >> 2;
    int tg = lane & 3;
    int wm = warp & 1;
    int wn = warp >> 1;
    int mW = wm * 64;
    int nW = wn * 32;

    int amM = tid & 127;
    int akq = tid >> 7;
    const bool bContigN = (csB == 1);

    float acc[4][4][4];
    #pragma unroll
    for (int i = 0; i < 4; i++)
        #pragma unroll
        for (int j = 0; j < 4; j++)
            #pragma unroll
            for (int l = 0; l < 4; l++) acc[i][j][l] = 0.f;

    float4 va[2], vb[2];

    auto loadTile = [&](int k0) {
        #pragma unroll
        for (int i = 0; i < 2; i++) {
            int kq = akq + i * 2;
            int gm = m0 + amM, gk = k0 + kq * 4;
            float4 v = make_float4(0.f, 0.f, 0.f, 0.f);
            if (gm < M) {
                if (csA == 1 && gk + 4 <= K) {
                    v = *(const float4*)(Ab + (long long)gm * rsA + gk);
                } else {
                    float* pv = (float*)&v;
                    #pragma unroll
                    for (int j = 0; j < 4; j++)
                        if (gk + j < K) pv[j] = Ab[(long long)gm * rsA + (long long)(gk + j) * csA];
                }
            }
            va[i] = v;
        }
        #pragma unroll
        for (int i = 0; i < 2; i++) {
            int slot = tid + i * 256;
            float4 v = make_float4(0.f, 0.f, 0.f, 0.f);
            if (bContigN) {
                int kk = slot >> 5, nq = slot & 31;
                int gk = k0 + kk, gn = n0 + nq * 4;
                if (gk < K) {
                    if (gn + 4 <= N) {
                        v = *(const float4*)(Bb + (long long)gk * rsB + gn);
                    } else {
                        float* pv = (float*)&v;
                        #pragma unroll
                        for (int j = 0; j < 4; j++)
                            if (gn + j < N) pv[j] = Bb[(long long)gk * rsB + (long long)(gn + j)];
                    }
                }
            } else {
                int nn = slot >> 2, kq2 = slot & 3;
                int gn = n0 + nn, gk = k0 + kq2 * 4;
                if (gn < N) {
                    if (rsB == 1 && gk + 4 <= K) {
                        v = *(const float4*)(Bb + (long long)gn * csB + gk);
                    } else {
                        float* pv = (float*)&v;
                        #pragma unroll
                        for (int j = 0; j < 4; j++)
                            if (gk + j < K) pv[j] = Bb[(long long)(gk + j) * rsB + (long long)gn * csB];
                    }
                }
            }
            vb[i] = v;
        }
    };

    auto storeTile = [&](int bsel) {
        #pragma unroll
        for (int i = 0; i < 2; i++) {
            int kq = akq + i * 2;
            const float* pv = (const float*)&va[i];
            #pragma unroll
            for (int j = 0; j < 4; j++)
                As[bsel][kq * 4 + j][amM] = f2tf32(pv[j]);
        }
        #pragma unroll
        for (int i = 0; i < 2; i++) {
            int slot = tid + i * 256;
            const float* pv = (const float*)&vb[i];
            if (bContigN) {
                int kk = slot >> 5, nq = slot & 31;
                uint4 u;
                u.x = f2tf32(pv[0]); u.y = f2tf32(pv[1]);
                u.z = f2tf32(pv[2]); u.w = f2tf32(pv[3]);
                *(uint4*)&Bs[bsel][kk][nq * 4] = u;
            } else {
                int nn = slot >> 2, kq2 = slot & 3;
                #pragma unroll
                for (int j = 0; j < 4; j++)
                    Bs[bsel][kq2 * 4 + j][nn] = f2tf32(pv[j]);
            }
        }
    };

    auto compute = [&](int bsel) {
        #pragma unroll
        for (int ks = 0; ks < 2; ks++) {
            int kk = ks * 8;
            uint32_t af[4][4];
            #pragma unroll
            for (int mi = 0; mi < 4; mi++) {
                int mb = mW + mi * 16;
                af[mi][0] = As[bsel][kk + tg][mb + g];
                af[mi][1] = As[bsel][kk + tg][mb + g + 8];
                af[mi][2] = As[bsel][kk + tg + 4][mb + g];
                af[mi][3] = As[bsel][kk + tg + 4][mb + g + 8];
            }
            uint32_t bf[4][2];
            #pragma unroll
            for (int ni = 0; ni < 4; ni++) {
                int nb = nW + ni * 8;
                bf[ni][0] = Bs[bsel][kk + tg][nb + g];
                bf[ni][1] = Bs[bsel][kk + tg + 4][nb + g];
            }
            #pragma unroll
            for (int mi = 0; mi < 4; mi++)
                #pragma unroll
                for (int ni = 0; ni < 4; ni++)
                    mma_tf32(acc[mi][ni], af[mi], bf[ni]);
        }
    };

    int nk = (K + BKT - 1) / BKT;
    loadTile(0);
    storeTile(0);
    __syncthreads();
    int buf = 0;
    for (int i = 0; i < nk; i++) {
        if (i + 1 < nk) loadTile((i + 1) * BKT);
        compute(buf);
        if (i + 1 < nk) {
            storeTile(buf ^ 1);
            buf ^= 1;
            __syncthreads();
        }
    }

    bool vecC = (csC == 1) && ((rsC & 1) == 0);
    #pragma unroll
    for (int mi = 0; mi < 4; mi++) {
        #pragma unroll
        for (int ni = 0; ni < 4; ni++) {
            #pragma unroll
            for (int half = 0; half < 2; half++) {
                int r = m0 + mW + mi * 16 + g + half * 8;
                if (r >= M) continue;
                int c = n0 + nW + ni * 8 + tg * 2;
                float v0 = alpha * acc[mi][ni][half * 2];
                float v1 = alpha * acc[mi][ni][half * 2 + 1];
                if (Bib) {
                    if (c < N)     v0 += Bib[(long long)r * rsBi + (long long)c * csBi];
                    if (c + 1 < N) v1 += Bib[(long long)r * rsBi + (long long)(c + 1) * csBi];
                }
                if (vecC && c + 2 <= N) {
                    float2 w; w.x = v0; w.y = v1;
                    *(float2*)(Cb + (long long)r * rsC + c) = w;
                } else {
                    if (c < N)     Cb[(long long)r * rsC + (long long)c * csC] = v0;
                    if (c + 1 < N) Cb[(long long)r * rsC + (long long)(c + 1) * csC] = v1;
                }
            }
        }
    }
}

// ---------------- pooling ----------------------------------------------------
__global__ void pool_kernel(const float* __restrict__ q, float* __restrict__ adla)
{
    long long t = (long long)blockIdx.x * blockDim.x + threadIdx.x;
    if (t >= (long long)BATCH * ADLAV * DIMV) return;
    int c = (int)(t % DIMV);
    int a = (int)((t / DIMV) % ADLAV);
    int b = (int)(t / ((long long)DIMV * ADLAV));
    int p0 = a / 49, p1 = (a / 7) % 7, p2 = a % 7;
    float s = 0.f;
    #pragma unroll
    for (int r0 = 0; r0 < 2; r0++)
        #pragma unroll
        for (int r1 = 0; r1 < 2; r1++)
            #pragma unroll
            for (int r2 = 0; r2 < 2; r2++) {
                int i = p0 * 2 + r0, j = p1 * 2 + r1, k = p2 * 2 + r2;
                int n = (i * HWD + j) * HWD + k;
                s += q[((long long)b * NTOK + n) * DIMV + c];
            }
    adla[t] = s * 0.125f;
}

// ---------------- trilinear weights (7 -> 14) --------------------------------
__device__ __forceinline__ void lin_w(int o, int& x0, int& x1, float& w)
{
    float x = 0.5f * (float)o - 0.25f;
    x = fminf(fmaxf(x, 0.f), 6.f);
    x0 = (int)floorf(x);
    if (x0 > 6) x0 = 6;
    x1 = min(x0 + 1, 6);
    w = x - (float)x0;
}

__global__ void biasprep(const float* __restrict__ an, const float* __restrict__ na,
                         const float* __restrict__ ah, const float* __restrict__ aw,
                         const float* __restrict__ ad, const float* __restrict__ ha,
                         const float* __restrict__ wa, const float* __restrict__ da,
                         float* __restrict__ b1, float* __restrict__ b2)
{
    int haid = blockIdx.x;
    int h = haid / ADLAV;
    int a = haid % ADLAV;
    __shared__ float s_an[343], s_na[343];
    __shared__ float s_ax[3][14];
    __shared__ float s_xa[3][14];
    int tid = threadIdx.x;
    const float* anb = an + (long long)haid * 343;
    const float* nab = na + (long long)haid * 343;
    for (int i = tid; i < 343; i += 256) { s_an[i] = anb[i]; s_na[i] = nab[i]; }
    if (tid < 14) {
        s_ax[0][tid] = ah[(long long)haid * HWD + tid];
        s_ax[1][tid] = aw[(long long)haid * HWD + tid];
        s_ax[2][tid] = ad[(long long)haid * HWD + tid];
        s_xa[0][tid] = ha[((long long)h * HWD + tid) * ADLAV + a];
        s_xa[1][tid] = wa[((long long)h * HWD + tid) * ADLAV + a];
        s_xa[2][tid] = da[((long long)h * HWD + tid) * ADLAV + a];
    }
    __syncthreads();
    long long base = (long long)haid * NTOK;
    for (int n = tid; n < NTOK; n += 256) {
        int i = n / (HWD * HWD), j = (n / HWD) % HWD, k = n % HWD;
        int i0, i1, j0, j1, k0, k1;
        float wi, wj, wk;
        lin_w(i, i0, i1, wi);
        lin_w(j, j0, j1, wj);
        lin_w(k, k0, k1, wk);
        float v1, v2;
        {
            const float* t = s_an;
            float c00 = (1.f-wk)*t[(i0*7+j0)*7+k0] + wk*t[(i0*7+j0)*7+k1];
            float c01 = (1.f-wk)*t[(i0*7+j1)*7+k0] + wk*t[(i0*7+j1)*7+k1];
            float c10 = (1.f-wk)*t[(i1*7+j0)*7+k0] + wk*t[(i1*7+j0)*7+k1];
            float c11 = (1.f-wk)*t[(i1*7+j1)*7+k0] + wk*t[(i1*7+j1)*7+k1];
            v1 = (1.f-wi)*((1.f-wj)*c00 + wj*c01) + wi*((1.f-wj)*c10 + wj*c11);
        }
        {
            const float* t = s_na;
            float c00 = (1.f-wk)*t[(i0*7+j0)*7+k0] + wk*t[(i0*7+j0)*7+k1];
            float c01 = (1.f-wk)*t[(i0*7+j1)*7+k0] + wk*t[(i0*7+j1)*7+k1];
            float c10 = (1.f-wk)*t[(i1*7+j0)*7+k0] + wk*t[(i1*7+j0)*7+k1];
            float c11 = (1.f-wk)*t[(i1*7+j1)*7+k0] + wk*t[(i1*7+j1)*7+k1];
            v2 = (1.f-wi)*((1.f-wj)*c00 + wj*c01) + wi*((1.f-wj)*c10 + wj*c11);
        }
        v1 += s_ax[0][i] + s_ax[1][j] + s_ax[2][k];
        v2 += s_xa[0][i] + s_xa[1][j] + s_xa[2][k];
        b1[base + n] = v1;
        b2[base + n] = v2;
    }
}

// tiled transpose: b2[h,a,n] -> b2t[h,n,a]
__global__ void transpose_b2(const float* __restrict__ b2, float* __restrict__ b2t)
{
    __shared__ float t[32][33];
    int h = blockIdx.z;
    int a0 = blockIdx.y * 32, n0 = blockIdx.x * 32;
    int x = threadIdx.x, y = threadIdx.y;
    #pragma unroll
    for (int yy = y; yy < 32; yy += 8) {
        int a = a0 + yy, n = n0 + x;
        if (a < ADLAV && n < NTOK)
            t[yy][x] = b2[((long long)h * ADLAV + a) * NTOK + n];
    }
    __syncthreads();
    #pragma unroll
    for (int yy = y; yy < 32; yy += 8) {
        int n = n0 + yy, a = a0 + x;
        if (a < ADLAV && n < NTOK)
            b2t[((long long)h * NTOK + n) * ADLAV + a] = t[x][yy];
    }
}

// ---------------- depthwise 3x3x3 conv (SAME), add into out ------------------
__global__ void dwc_add(const float* __restrict__ kv, const float* __restrict__ w,
                        const float* __restrict__ bvec, float* __restrict__ out)
{
    long long t = (long long)blockIdx.x * blockDim.x + threadIdx.x;
    if (t >= (long long)BATCH * NTOK * DIMV) return;
    int c = (int)(t % DIMV);
    int n = (int)((t / DIMV) % NTOK);
    int b = (int)(t / ((long long)DIMV * NTOK));
    int i = n / (HWD * HWD), j = (n / HWD) % HWD, k = n % HWD;
    float acc = bvec[c];
    const float* wc = w + (long long)c * 27;
    #pragma unroll
    for (int di = -1; di <= 1; di++) {
        int ii = i + di;
        if (ii < 0 || ii >= HWD) continue;
        #pragma unroll
        for (int dj = -1; dj <= 1; dj++) {
            int jj = j + dj;
            if (jj < 0 || jj >= HWD) continue;
            #pragma unroll
            for (int dk = -1; dk <= 1; dk++) {
                int kk = k + dk;
                if (kk < 0 || kk >= HWD) continue;
                int nn = (ii * HWD + jj) * HWD + kk;
                acc += kv[((long long)b * NTOK + nn) * (2 * DIMV) + DIMV + c]
                     * wc[(di + 1) * 9 + (dj + 1) * 3 + (dk + 1)];
            }
        }
    }
    out[t] += acc;
}

// ---------------- host launcher ----------------------------------------------
static inline dim3 gT64(int M, int N, int Z) {
    return dim3((unsigned)((N + BNT - 1) / BNT), (unsigned)((M + BMT - 1) / BMT), (unsigned)Z);
}
static inline dim3 gT128(int M, int N) {
    return dim3((unsigned)((N + BNT2 - 1) / BNT2), (unsigned)((M + BMT - 1) / BMT), 1);
}

extern "C" void kernel_launch(void* const* d_in, const int* in_sizes, int n_in,
                              void* d_out, int out_size)
{
    const float* x     = (const float*)d_in[0];
    const float* Wq    = (const float*)d_in[1];
    const float* Wkv   = (const float*)d_in[2];
    const float* Wproj = (const float*)d_in[3];
    const float* bproj = (const float*)d_in[4];
    const float* dwcw  = (const float*)d_in[5];
    const float* dwcb  = (const float*)d_in[6];
    const float* an    = (const float*)d_in[7];
    const float* na    = (const float*)d_in[8];
    const float* ah    = (const float*)d_in[9];
    const float* aw    = (const float*)d_in[10];
    const float* ad    = (const float*)d_in[11];
    const float* ha    = (const float*)d_in[12];
    const float* wa    = (const float*)d_in[13];
    const float* da    = (const float*)d_in[14];
    float* out = (float*)d_out;

    void *pq, *pkv, *padla, *pb1, *pb2, *pb2t, *plog, *pav, *pao;
    cudaGetSymbolAddress(&pq, g_q);
    cudaGetSymbolAddress(&pkv, g_kv);
    cudaGetSymbolAddress(&padla, g_adla);
    cudaGetSymbolAddress(&pb1, g_bias1);
    cudaGetSymbolAddress(&pb2, g_bias2);
    cudaGetSymbolAddress(&pb2t, g_bias2t);
    cudaGetSymbolAddress(&plog, g_logits);
    cudaGetSymbolAddress(&pav, g_adlav);
    cudaGetSymbolAddress(&pao, g_attnout);
    float* q    = (float*)pq;
    float* kv   = (float*)pkv;
    float* adla = (float*)padla;
    float* b1   = (float*)pb1;
    float* b2   = (float*)pb2;
    float* b2t  = (float*)pb2t;
    float* lg   = (float*)plog;
    float* av   = (float*)pav;
    float* ao   = (float*)pao;

    // 1. q = x @ Wq
    tgemm128<<<gT128(BN_TOT, DIMV), 256>>>(BN_TOT, DIMV, DIMV,
        x,  DIMV, 1,
        Wq, DIMV, 1,
        q,  DIMV, 1,
        nullptr, 0, 0, 1.f);

    // 2. kv = x @ Wkv
    tgemm128<<<gT128(BN_TOT, 2 * DIMV), 256>>>(BN_TOT, 2 * DIMV, DIMV,
        x,   DIMV,    1,
        Wkv, 2 * DIMV, 1,
        kv,  2 * DIMV, 1,
        nullptr, 0, 0, 1.f);

    // 3. adla pooling
    {
        long long tot = (long long)BATCH * ADLAV * DIMV;
        pool_kernel<<<(unsigned)((tot + 255) / 256), 256>>>(q, adla);
    }

    // 4. bias tables + transpose
    biasprep<<<HEADS * ADLAV, 256>>>(an, na, ah, aw, ad, ha, wa, da, b1, b2);
    transpose_b2<<<dim3((NTOK + 31) / 32, (ADLAV + 31) / 32, HEADS), dim3(32, 8)>>>(b2, b2t);

    // 5. attn1 logits: [343,2744] = [343,48] @ [48,2744] * SCALE + bias1
    tgemm64<<<gT64(ADLAV, NTOK, BATCH * HEADS), 256>>>(ADLAV, NTOK, HD,
        adla, DIMV, 1, (long long)ADLAV * DIMV, HD,
        kv,   1, 2 * DIMV, (long long)NTOK * 2 * DIMV, HD,
        lg,   NTOK, 1, (long long)HEADS * ADLAV * NTOK, (long long)ADLAV * NTOK,
        b1,   NTOK, 1, (long long)ADLAV * NTOK,
        SCALEV);

    // 6. adla_v = softmax(lg) @ V — single-pass fused (exp + ones-col rowsum)
    pv_exp<<<gT64(ADLAV, HD, BATCH * HEADS), 256>>>(ADLAV, HD, NTOK,
        lg,        NTOK, (long long)HEADS * ADLAV * NTOK, (long long)ADLAV * NTOK,
        kv + DIMV, 2 * DIMV, (long long)NTOK * 2 * DIMV, HD,
        av,        HD, (long long)HEADS * ADLAV * HD, (long long)ADLAV * HD);

    // 7. attn2 logits: [2744,343] = [2744,48] @ [48,343] * SCALE + bias2t (padded rows)
    tgemm64<<<gT64(NTOK, ADLAV, BATCH * HEADS), 256>>>(NTOK, ADLAV, HD,
        q,    DIMV, 1, (long long)NTOK * DIMV, HD,
        adla, 1, DIMV, (long long)ADLAV * DIMV, HD,
        lg,   LG2PAD, 1, (long long)HEADS * NTOK * LG2PAD, (long long)NTOK * LG2PAD,
        b2t,  ADLAV, 1, (long long)NTOK * ADLAV,
        SCALEV);

    // 8. attnout = softmax(lg) @ adla_v — single-pass fused
    pv_exp<<<gT64(NTOK, HD, BATCH * HEADS), 256>>>(NTOK, HD, ADLAV,
        lg, LG2PAD, (long long)HEADS * NTOK * LG2PAD, (long long)NTOK * LG2PAD,
        av, HD, (long long)HEADS * ADLAV * HD, (long long)ADLAV * HD,
        ao, DIMV, (long long)NTOK * DIMV, HD);

    // 9. depthwise conv 3x3x3 of v, added into attnout
    {
        long long tot = (long long)BATCH * NTOK * DIMV;
        dwc_add<<<(unsigned)((tot + 255) / 256), 256>>>(kv, dwcw, dwcb, ao);
    }

    // 10. final: out = attnout @ Wproj + bproj
    tgemm128<<<gT128(BN_TOT, DIMV), 256>>>(BN_TOT, DIMV, DIMV,
        ao,    DIMV, 1,
        Wproj, DIMV, 1,
        out,   DIMV, 1,
        bproj, 0, 1,
        1.f);

    (void)in_sizes; (void)n_in; (void)out_size;
}

// round 12
// speedup vs baseline: 1.6761x; 1.4804x over previous
#include <cuda_runtime.h>
#include <math.h>
#include <stdint.h>

#define HEADS   8
#define DIMV    384
#define HD      48
#define ADLAV   343
#define HWD     14
#define NTOK    2744
#define BATCH   8
#define SCALEV  0.14433756729740645f   // 48^-0.5

#define BN_TOT  (BATCH * NTOK)         // 21952

// ---------------- scratch (static device allocations) ------------------------
__device__ float g_q[BATCH * NTOK * DIMV];
__device__ float g_kv[BATCH * NTOK * 2 * DIMV];
__device__ float g_adla[BATCH * ADLAV * DIMV];
__device__ float g_bias1[HEADS * ADLAV * NTOK];
__device__ float g_bias2[HEADS * ADLAV * NTOK];      // [h,a,n]
__device__ float g_bias2t[HEADS * ADLAV * NTOK];     // [h,n,a]
__device__ float g_adlav[BATCH * HEADS * ADLAV * HD];
__device__ float g_attnout[BATCH * NTOK * DIMV];

// ---------------- tf32 helpers ----------------------------------------------
__device__ __forceinline__ uint32_t f2tf32(float x) {
    uint32_t r;
    asm("cvt.rna.tf32.f32 %0, %1;" : "=r"(r) : "f"(x));
    return r;
}

__device__ __forceinline__ void mma_tf32(float* c, const uint32_t* a, const uint32_t* b) {
    asm volatile(
        "mma.sync.aligned.m16n8k8.row.col.f32.tf32.tf32.f32 "
        "{%0,%1,%2,%3}, {%4,%5,%6,%7}, {%8,%9}, {%0,%1,%2,%3};\n"
        : "+f"(c[0]), "+f"(c[1]), "+f"(c[2]), "+f"(c[3])
        : "r"(a[0]), "r"(a[1]), "r"(a[2]), "r"(a[3]), "r"(b[0]), "r"(b[1]));
}

// ============ flash_ns: fully fused attention, NO max subtraction ============
// O[r,:] = (sum_n exp(s[r,n]) * V[n,:]) / (sum_n exp(s[r,n]))
// s = SCALE*(Q @ K^T) + bias, computed chunk-by-chunk (64 keys) with the
// attn_ps mma chain (R7-verified); exp without max (R10-verified: logits
// bounded); P re-fragmented via warp-private smem (R6-verified layout);
// row sums accumulated per-thread fp32, one shfl reduce at the end.
#define KSP 72
#define VSP 56
#define PSP 24
#define FSM ((48*KSP + 64*VSP + 8*64*PSP) * 4)

__global__ __launch_bounds__(256) void flash_ns(
    const float* __restrict__ Qp, long long qB, long long qH, int qR,
    const float* __restrict__ Kp, long long kB, long long kH, int kR,
    const float* __restrict__ Vp, long long vB, long long vH, int vR, int vC,
    const float* __restrict__ Bp, long long bHs, int bR,
    float* __restrict__ Op, long long oB, long long oH, int oR,
    int M, int NK)
{
    extern __shared__ float sm[];
    float* Ks = sm;                       // [48][KSP], d-major
    float* Vs = sm + 48 * KSP;            // [64][VSP], n-major
    float* Ps = sm + 48 * KSP + 64 * VSP; // 8 warps x [64][PSP]

    int bb = blockIdx.y >> 3, hh = blockIdx.y & 7;
    int m0 = blockIdx.x * 128;
    const float* Qb = Qp + bb * qB + hh * qH;
    const float* Kb = Kp + bb * kB + hh * kH;
    const float* Vb = Vp + bb * vB + hh * vH + vC;
    const float* Bb = Bp + hh * bHs;
    float* Ob = Op + bb * oB + hh * oH;

    int tid = threadIdx.x, warp = tid >> 5, lane = tid & 31;
    int g = lane >> 2, tg = lane & 3;
    int r0 = m0 + warp * 16 + g;
    int r1 = r0 + 8;

    // Q fragments (unscaled tf32; SCALE applied after mma, as in tgemm64)
    uint32_t qf[6][4];
    #pragma unroll
    for (int ks = 0; ks < 6; ks++) {
        int k0 = ks * 8 + tg, k1 = k0 + 4;
        qf[ks][0] = (r0 < M) ? f2tf32(Qb[(long long)r0 * qR + k0]) : 0u;
        qf[ks][1] = (r1 < M) ? f2tf32(Qb[(long long)r1 * qR + k0]) : 0u;
        qf[ks][2] = (r0 < M) ? f2tf32(Qb[(long long)r0 * qR + k1]) : 0u;
        qf[ks][3] = (r1 < M) ? f2tf32(Qb[(long long)r1 * qR + k1]) : 0u;
    }

    float oacc[6][4];
    #pragma unroll
    for (int i = 0; i < 6; i++)
        #pragma unroll
        for (int j = 0; j < 4; j++) oacc[i][j] = 0.f;
    float rs0 = 0.f, rs1 = 0.f;

    float* Pw = Ps + warp * (64 * PSP);
    int nn = tid >> 2, f0 = tid & 3;
    int nch = (NK + 63) >> 6;

    for (int ch = 0; ch < nch; ch++) {
        int n0 = ch * 64;
        int lim = min(64, NK - n0);

        // ---- load K chunk -> Ks[d][n], V chunk -> Vs[n][d] ----
        __syncthreads();
        #pragma unroll
        for (int j = 0; j < 3; j++) {
            int dbase = (f0 + j * 4) * 4;
            float4 v = make_float4(0.f, 0.f, 0.f, 0.f);
            float4 w = make_float4(0.f, 0.f, 0.f, 0.f);
            if (nn < lim) {
                v = *(const float4*)(Kb + (long long)(n0 + nn) * kR + dbase);
                w = *(const float4*)(Vb + (long long)(n0 + nn) * vR + dbase);
            }
            Ks[(dbase + 0) * KSP + nn] = __uint_as_float(f2tf32(v.x));
            Ks[(dbase + 1) * KSP + nn] = __uint_as_float(f2tf32(v.y));
            Ks[(dbase + 2) * KSP + nn] = __uint_as_float(f2tf32(v.z));
            Ks[(dbase + 3) * KSP + nn] = __uint_as_float(f2tf32(v.w));
            uint4 u;
            u.x = f2tf32(w.x); u.y = f2tf32(w.y); u.z = f2tf32(w.z); u.w = f2tf32(w.w);
            *(uint4*)&Vs[nn * VSP + dbase] = u;
        }
        __syncthreads();

        // ---- S = SCALE*(Q @ K^T) + bias (attn_ps chain) ----
        float s[8][4];
        #pragma unroll
        for (int ni = 0; ni < 8; ni++)
            #pragma unroll
            for (int l = 0; l < 4; l++) s[ni][l] = 0.f;
        #pragma unroll
        for (int ks = 0; ks < 6; ks++) {
            #pragma unroll
            for (int ni = 0; ni < 8; ni++) {
                uint32_t bf[2];
                bf[0] = __float_as_uint(Ks[(ks * 8 + tg) * KSP + ni * 8 + g]);
                bf[1] = __float_as_uint(Ks[(ks * 8 + tg + 4) * KSP + ni * 8 + g]);
                mma_tf32(s[ni], qf[ks], bf);
            }
        }
        #pragma unroll
        for (int ni = 0; ni < 8; ni++) {
            int c0 = n0 + ni * 8 + 2 * tg;
            bool v0 = c0 < NK, v1 = (c0 + 1) < NK;
            float b00 = 0.f, b01 = 0.f, b10 = 0.f, b11 = 0.f;
            if (r0 < M) {
                if (v0) b00 = Bb[(long long)r0 * bR + c0];
                if (v1) b01 = Bb[(long long)r0 * bR + c0 + 1];
            }
            if (r1 < M) {
                if (v0) b10 = Bb[(long long)r1 * bR + c0];
                if (v1) b11 = Bb[(long long)r1 * bR + c0 + 1];
            }
            s[ni][0] = v0 ? SCALEV * s[ni][0] + b00 : -1e30f;
            s[ni][1] = v1 ? SCALEV * s[ni][1] + b01 : -1e30f;
            s[ni][2] = v0 ? SCALEV * s[ni][2] + b10 : -1e30f;
            s[ni][3] = v1 ? SCALEV * s[ni][3] + b11 : -1e30f;
        }

        // ---- exp (no max) + per-thread rowsum partials ----
        #pragma unroll
        for (int ni = 0; ni < 8; ni++) {
            float p0 = __expf(s[ni][0]);
            float p1 = __expf(s[ni][1]);
            float p2 = __expf(s[ni][2]);
            float p3 = __expf(s[ni][3]);
            s[ni][0] = p0; s[ni][1] = p1; s[ni][2] = p2; s[ni][3] = p3;
            rs0 += p0 + p1;
            rs1 += p2 + p3;
        }

        // ---- P -> warp-private smem (R6 layout) ----
        #pragma unroll
        for (int ni = 0; ni < 8; ni++) {
            int c = ni * 8 + 2 * tg;
            Pw[c * PSP + g]           = __uint_as_float(f2tf32(s[ni][0]));
            Pw[(c + 1) * PSP + g]     = __uint_as_float(f2tf32(s[ni][1]));
            Pw[c * PSP + g + 8]       = __uint_as_float(f2tf32(s[ni][2]));
            Pw[(c + 1) * PSP + g + 8] = __uint_as_float(f2tf32(s[ni][3]));
        }
        __syncwarp();

        // ---- O~ += P @ V ----
        #pragma unroll
        for (int ks = 0; ks < 8; ks++) {
            uint32_t af[4];
            af[0] = __float_as_uint(Pw[(ks * 8 + tg) * PSP + g]);
            af[1] = __float_as_uint(Pw[(ks * 8 + tg) * PSP + g + 8]);
            af[2] = __float_as_uint(Pw[(ks * 8 + tg + 4) * PSP + g]);
            af[3] = __float_as_uint(Pw[(ks * 8 + tg + 4) * PSP + g + 8]);
            #pragma unroll
            for (int ni = 0; ni < 6; ni++) {
                uint32_t bf[2];
                bf[0] = __float_as_uint(Vs[(ks * 8 + tg) * VSP + ni * 8 + g]);
                bf[1] = __float_as_uint(Vs[(ks * 8 + tg + 4) * VSP + ni * 8 + g]);
                mma_tf32(oacc[ni], af, bf);
            }
        }
    }

    // ---- reduce row sums over tg lanes, normalize, store ----
    rs0 += __shfl_xor_sync(0xffffffffu, rs0, 1);
    rs0 += __shfl_xor_sync(0xffffffffu, rs0, 2);
    rs1 += __shfl_xor_sync(0xffffffffu, rs1, 1);
    rs1 += __shfl_xor_sync(0xffffffffu, rs1, 2);
    float inv0 = 1.f / rs0;
    float inv1 = 1.f / rs1;
    #pragma unroll
    for (int ni = 0; ni < 6; ni++) {
        int d = ni * 8 + tg * 2;
        if (r0 < M) {
            float2 w; w.x = oacc[ni][0] * inv0; w.y = oacc[ni][1] * inv0;
            *(float2*)(Ob + (long long)r0 * oR + d) = w;
        }
        if (r1 < M) {
            float2 w; w.x = oacc[ni][2] * inv1; w.y = oacc[ni][3] * inv1;
            *(float2*)(Ob + (long long)r1 * oR + d) = w;
        }
    }
}

// ============ tgemm128: tile 128x128, BK=16 (projections, csB=1) =============
#define BMT 128
#define BNT2 128
#define BKT 16
#define PP  136
__global__ __launch_bounds__(256) void tgemm128(int M, int N, int K,
    const float* __restrict__ A, long long rsA, long long csA,
    const float* __restrict__ B, long long rsB, long long csB,
    float* __restrict__ C, long long rsC, long long csC,
    const float* __restrict__ Bi, long long rsBi, long long csBi,
    float alpha)
{
    __shared__ uint32_t As[2][BKT][PP];
    __shared__ uint32_t Bs[2][BKT][PP];

    const float* Ab = A;
    const float* Bb = B;
    float*       Cb = C;
    const float* Bib = Bi;

    int m0 = blockIdx.y * BMT;
    int n0 = blockIdx.x * BNT2;
    int tid  = threadIdx.x;
    int warp = tid >> 5;
    int lane = tid & 31;
    int g  = lane >> 2;
    int tg = lane & 3;
    int wm = warp & 1;
    int wn = warp >> 1;
    int mW = wm * 64;
    int nW = wn * 32;

    int amM = tid & 127;
    int akq = tid >> 7;
    const bool bContigN = (csB == 1);

    float acc[4][4][4];
    #pragma unroll
    for (int i = 0; i < 4; i++)
        #pragma unroll
        for (int j = 0; j < 4; j++)
            #pragma unroll
            for (int l = 0; l < 4; l++) acc[i][j][l] = 0.f;

    float4 va[2], vb[2];

    auto loadTile = [&](int k0) {
        #pragma unroll
        for (int i = 0; i < 2; i++) {
            int kq = akq + i * 2;
            int gm = m0 + amM, gk = k0 + kq * 4;
            float4 v = make_float4(0.f, 0.f, 0.f, 0.f);
            if (gm < M) {
                if (csA == 1 && gk + 4 <= K) {
                    v = *(const float4*)(Ab + (long long)gm * rsA + gk);
                } else {
                    float* pv = (float*)&v;
                    #pragma unroll
                    for (int j = 0; j < 4; j++)
                        if (gk + j < K) pv[j] = Ab[(long long)gm * rsA + (long long)(gk + j) * csA];
                }
            }
            va[i] = v;
        }
        #pragma unroll
        for (int i = 0; i < 2; i++) {
            int slot = tid + i * 256;
            float4 v = make_float4(0.f, 0.f, 0.f, 0.f);
            if (bContigN) {
                int kk = slot >> 5, nq = slot & 31;
                int gk = k0 + kk, gn = n0 + nq * 4;
                if (gk < K) {
                    if (gn + 4 <= N) {
                        v = *(const float4*)(Bb + (long long)gk * rsB + gn);
                    } else {
                        float* pv = (float*)&v;
                        #pragma unroll
                        for (int j = 0; j < 4; j++)
                            if (gn + j < N) pv[j] = Bb[(long long)gk * rsB + (long long)(gn + j)];
                    }
                }
            } else {
                int nnn = slot >> 2, kq2 = slot & 3;
                int gn = n0 + nnn, gk = k0 + kq2 * 4;
                if (gn < N) {
                    if (rsB == 1 && gk + 4 <= K) {
                        v = *(const float4*)(Bb + (long long)gn * csB + gk);
                    } else {
                        float* pv = (float*)&v;
                        #pragma unroll
                        for (int j = 0; j < 4; j++)
                            if (gk + j < K) pv[j] = Bb[(long long)(gk + j) * rsB + (long long)gn * csB];
                    }
                }
            }
            vb[i] = v;
        }
    };

    auto storeTile = [&](int bsel) {
        #pragma unroll
        for (int i = 0; i < 2; i++) {
            int kq = akq + i * 2;
            const float* pv = (const float*)&va[i];
            #pragma unroll
            for (int j = 0; j < 4; j++)
                As[bsel][kq * 4 + j][amM] = f2tf32(pv[j]);
        }
        #pragma unroll
        for (int i = 0; i < 2; i++) {
            int slot = tid + i * 256;
            const float* pv = (const float*)&vb[i];
            if (bContigN) {
                int kk = slot >> 5, nq = slot & 31;
                uint4 u;
                u.x = f2tf32(pv[0]); u.y = f2tf32(pv[1]);
                u.z = f2tf32(pv[2]); u.w = f2tf32(pv[3]);
                *(uint4*)&Bs[bsel][kk][nq * 4] = u;
            } else {
                int nnn = slot >> 2, kq2 = slot & 3;
                #pragma unroll
                for (int j = 0; j < 4; j++)
                    Bs[bsel][kq2 * 4 + j][nnn] = f2tf32(pv[j]);
            }
        }
    };

    auto compute = [&](int bsel) {
        #pragma unroll
        for (int ks = 0; ks < 2; ks++) {
            int kk = ks * 8;
            uint32_t af[4][4];
            #pragma unroll
            for (int mi = 0; mi < 4; mi++) {
                int mb = mW + mi * 16;
                af[mi][0] = As[bsel][kk + tg][mb + g];
                af[mi][1] = As[bsel][kk + tg][mb + g + 8];
                af[mi][2] = As[bsel][kk + tg + 4][mb + g];
                af[mi][3] = As[bsel][kk + tg + 4][mb + g + 8];
            }
            uint32_t bf[4][2];
            #pragma unroll
            for (int ni = 0; ni < 4; ni++) {
                int nb = nW + ni * 8;
                bf[ni][0] = Bs[bsel][kk + tg][nb + g];
                bf[ni][1] = Bs[bsel][kk + tg + 4][nb + g];
            }
            #pragma unroll
            for (int mi = 0; mi < 4; mi++)
                #pragma unroll
                for (int ni = 0; ni < 4; ni++)
                    mma_tf32(acc[mi][ni], af[mi], bf[ni]);
        }
    };

    int nk = (K + BKT - 1) / BKT;
    loadTile(0);
    storeTile(0);
    __syncthreads();
    int buf = 0;
    for (int i = 0; i < nk; i++) {
        if (i + 1 < nk) loadTile((i + 1) * BKT);
        compute(buf);
        if (i + 1 < nk) {
            storeTile(buf ^ 1);
            buf ^= 1;
            __syncthreads();
        }
    }

    bool vecC = (csC == 1) && ((rsC & 1) == 0);
    #pragma unroll
    for (int mi = 0; mi < 4; mi++) {
        #pragma unroll
        for (int ni = 0; ni < 4; ni++) {
            #pragma unroll
            for (int half = 0; half < 2; half++) {
                int r = m0 + mW + mi * 16 + g + half * 8;
                if (r >= M) continue;
                int c = n0 + nW + ni * 8 + tg * 2;
                float v0 = alpha * acc[mi][ni][half * 2];
                float v1 = alpha * acc[mi][ni][half * 2 + 1];
                if (Bib) {
                    if (c < N)     v0 += Bib[(long long)r * rsBi + (long long)c * csBi];
                    if (c + 1 < N) v1 += Bib[(long long)r * rsBi + (long long)(c + 1) * csBi];
                }
                if (vecC && c + 2 <= N) {
                    float2 w; w.x = v0; w.y = v1;
                    *(float2*)(Cb + (long long)r * rsC + c) = w;
                } else {
                    if (c < N)     Cb[(long long)r * rsC + (long long)c * csC] = v0;
                    if (c + 1 < N) Cb[(long long)r * rsC + (long long)(c + 1) * csC] = v1;
                }
            }
        }
    }
}

// ---------------- pooling ----------------------------------------------------
__global__ void pool_kernel(const float* __restrict__ q, float* __restrict__ adla)
{
    long long t = (long long)blockIdx.x * blockDim.x + threadIdx.x;
    if (t >= (long long)BATCH * ADLAV * DIMV) return;
    int c = (int)(t % DIMV);
    int a = (int)((t / DIMV) % ADLAV);
    int b = (int)(t / ((long long)DIMV * ADLAV));
    int p0 = a / 49, p1 = (a / 7) % 7, p2 = a % 7;
    float s = 0.f;
    #pragma unroll
    for (int r0 = 0; r0 < 2; r0++)
        #pragma unroll
        for (int r1 = 0; r1 < 2; r1++)
            #pragma unroll
            for (int r2 = 0; r2 < 2; r2++) {
                int i = p0 * 2 + r0, j = p1 * 2 + r1, k = p2 * 2 + r2;
                int n = (i * HWD + j) * HWD + k;
                s += q[((long long)b * NTOK + n) * DIMV + c];
            }
    adla[t] = s * 0.125f;
}

// ---------------- trilinear weights (7 -> 14) --------------------------------
__device__ __forceinline__ void lin_w(int o, int& x0, int& x1, float& w)
{
    float x = 0.5f * (float)o - 0.25f;
    x = fminf(fmaxf(x, 0.f), 6.f);
    x0 = (int)floorf(x);
    if (x0 > 6) x0 = 6;
    x1 = min(x0 + 1, 6);
    w = x - (float)x0;
}

__global__ void biasprep(const float* __restrict__ an, const float* __restrict__ na,
                         const float* __restrict__ ah, const float* __restrict__ aw,
                         const float* __restrict__ ad, const float* __restrict__ ha,
                         const float* __restrict__ wa, const float* __restrict__ da,
                         float* __restrict__ b1, float* __restrict__ b2)
{
    int haid = blockIdx.x;
    int h = haid / ADLAV;
    int a = haid % ADLAV;
    __shared__ float s_an[343], s_na[343];
    __shared__ float s_ax[3][14];
    __shared__ float s_xa[3][14];
    int tid = threadIdx.x;
    const float* anb = an + (long long)haid * 343;
    const float* nab = na + (long long)haid * 343;
    for (int i = tid; i < 343; i += 256) { s_an[i] = anb[i]; s_na[i] = nab[i]; }
    if (tid < 14) {
        s_ax[0][tid] = ah[(long long)haid * HWD + tid];
        s_ax[1][tid] = aw[(long long)haid * HWD + tid];
        s_ax[2][tid] = ad[(long long)haid * HWD + tid];
        s_xa[0][tid] = ha[((long long)h * HWD + tid) * ADLAV + a];
        s_xa[1][tid] = wa[((long long)h * HWD + tid) * ADLAV + a];
        s_xa[2][tid] = da[((long long)h * HWD + tid) * ADLAV + a];
    }
    __syncthreads();
    long long base = (long long)haid * NTOK;
    for (int n = tid; n < NTOK; n += 256) {
        int i = n / (HWD * HWD), j = (n / HWD) % HWD, k = n % HWD;
        int i0, i1, j0, j1, k0, k1;
        float wi, wj, wk;
        lin_w(i, i0, i1, wi);
        lin_w(j, j0, j1, wj);
        lin_w(k, k0, k1, wk);
        float v1, v2;
        {
            const float* t = s_an;
            float c00 = (1.f-wk)*t[(i0*7+j0)*7+k0] + wk*t[(i0*7+j0)*7+k1];
            float c01 = (1.f-wk)*t[(i0*7+j1)*7+k0] + wk*t[(i0*7+j1)*7+k1];
            float c10 = (1.f-wk)*t[(i1*7+j0)*7+k0] + wk*t[(i1*7+j0)*7+k1];
            float c11 = (1.f-wk)*t[(i1*7+j1)*7+k0] + wk*t[(i1*7+j1)*7+k1];
            v1 = (1.f-wi)*((1.f-wj)*c00 + wj*c01) + wi*((1.f-wj)*c10 + wj*c11);
        }
        {
            const float* t = s_na;
            float c00 = (1.f-wk)*t[(i0*7+j0)*7+k0] + wk*t[(i0*7+j0)*7+k1];
            float c01 = (1.f-wk)*t[(i0*7+j1)*7+k0] + wk*t[(i0*7+j1)*7+k1];
            float c10 = (1.f-wk)*t[(i1*7+j0)*7+k0] + wk*t[(i1*7+j0)*7+k1];
            float c11 = (1.f-wk)*t[(i1*7+j1)*7+k0] + wk*t[(i1*7+j1)*7+k1];
            v2 = (1.f-wi)*((1.f-wj)*c00 + wj*c01) + wi*((1.f-wj)*c10 + wj*c11);
        }
        v1 += s_ax[0][i] + s_ax[1][j] + s_ax[2][k];
        v2 += s_xa[0][i] + s_xa[1][j] + s_xa[2][k];
        b1[base + n] = v1;
        b2[base + n] = v2;
    }
}

// tiled transpose: b2[h,a,n] -> b2t[h,n,a]
__global__ void transpose_b2(const float* __restrict__ b2, float* __restrict__ b2t)
{
    __shared__ float t[32][33];
    int h = blockIdx.z;
    int a0 = blockIdx.y * 32, n0 = blockIdx.x * 32;
    int x = threadIdx.x, y = threadIdx.y;
    #pragma unroll
    for (int yy = y; yy < 32; yy += 8) {
        int a = a0 + yy, n = n0 + x;
        if (a < ADLAV && n < NTOK)
            t[yy][x] = b2[((long long)h * ADLAV + a) * NTOK + n];
    }
    __syncthreads();
    #pragma unroll
    for (int yy = y; yy < 32; yy += 8) {
        int n = n0 + yy, a = a0 + x;
        if (a < ADLAV && n < NTOK)
            b2t[((long long)h * NTOK + n) * ADLAV + a] = t[x][yy];
    }
}

// ---------------- depthwise 3x3x3 conv (SAME), add into out ------------------
__global__ void dwc_add(const float* __restrict__ kv, const float* __restrict__ w,
                        const float* __restrict__ bvec, float* __restrict__ out)
{
    long long t = (long long)blockIdx.x * blockDim.x + threadIdx.x;
    if (t >= (long long)BATCH * NTOK * DIMV) return;
    int c = (int)(t % DIMV);
    int n = (int)((t / DIMV) % NTOK);
    int b = (int)(t / ((long long)DIMV * NTOK));
    int i = n / (HWD * HWD), j = (n / HWD) % HWD, k = n % HWD;
    float acc = bvec[c];
    const float* wc = w + (long long)c * 27;
    #pragma unroll
    for (int di = -1; di <= 1; di++) {
        int ii = i + di;
        if (ii < 0 || ii >= HWD) continue;
        #pragma unroll
        for (int dj = -1; dj <= 1; dj++) {
            int jj = j + dj;
            if (jj < 0 || jj >= HWD) continue;
            #pragma unroll
            for (int dk = -1; dk <= 1; dk++) {
                int kk = k + dk;
                if (kk < 0 || kk >= HWD) continue;
                int nn = (ii * HWD + jj) * HWD + kk;
                acc += kv[((long long)b * NTOK + nn) * (2 * DIMV) + DIMV + c]
                     * wc[(di + 1) * 9 + (dj + 1) * 3 + (dk + 1)];
            }
        }
    }
    out[t] += acc;
}

// ---------------- host launcher ----------------------------------------------
static inline dim3 gT128(int M, int N) {
    return dim3((unsigned)((N + BNT2 - 1) / BNT2), (unsigned)((M + BMT - 1) / BMT), 1);
}

extern "C" void kernel_launch(void* const* d_in, const int* in_sizes, int n_in,
                              void* d_out, int out_size)
{
    const float* x     = (const float*)d_in[0];
    const float* Wq    = (const float*)d_in[1];
    const float* Wkv   = (const float*)d_in[2];
    const float* Wproj = (const float*)d_in[3];
    const float* bproj = (const float*)d_in[4];
    const float* dwcw  = (const float*)d_in[5];
    const float* dwcb  = (const float*)d_in[6];
    const float* an    = (const float*)d_in[7];
    const float* na    = (const float*)d_in[8];
    const float* ah    = (const float*)d_in[9];
    const float* aw    = (const float*)d_in[10];
    const float* ad    = (const float*)d_in[11];
    const float* ha    = (const float*)d_in[12];
    const float* wa    = (const float*)d_in[13];
    const float* da    = (const float*)d_in[14];
    float* out = (float*)d_out;

    void *pq, *pkv, *padla, *pb1, *pb2, *pb2t, *pav, *pao;
    cudaGetSymbolAddress(&pq, g_q);
    cudaGetSymbolAddress(&pkv, g_kv);
    cudaGetSymbolAddress(&padla, g_adla);
    cudaGetSymbolAddress(&pb1, g_bias1);
    cudaGetSymbolAddress(&pb2, g_bias2);
    cudaGetSymbolAddress(&pb2t, g_bias2t);
    cudaGetSymbolAddress(&pav, g_adlav);
    cudaGetSymbolAddress(&pao, g_attnout);
    float* q    = (float*)pq;
    float* kv   = (float*)pkv;
    float* adla = (float*)padla;
    float* b1   = (float*)pb1;
    float* b2   = (float*)pb2;
    float* b2t  = (float*)pb2t;
    float* av   = (float*)pav;
    float* ao   = (float*)pao;

    cudaFuncSetAttribute(flash_ns, cudaFuncAttributeMaxDynamicSharedMemorySize, FSM);

    // 1. q = x @ Wq
    tgemm128<<<gT128(BN_TOT, DIMV), 256>>>(BN_TOT, DIMV, DIMV,
        x,  DIMV, 1,
        Wq, DIMV, 1,
        q,  DIMV, 1,
        nullptr, 0, 0, 1.f);

    // 2. kv = x @ Wkv
    tgemm128<<<gT128(BN_TOT, 2 * DIMV), 256>>>(BN_TOT, 2 * DIMV, DIMV,
        x,   DIMV,    1,
        Wkv, 2 * DIMV, 1,
        kv,  2 * DIMV, 1,
        nullptr, 0, 0, 1.f);

    // 3. adla pooling
    {
        long long tot = (long long)BATCH * ADLAV * DIMV;
        pool_kernel<<<(unsigned)((tot + 255) / 256), 256>>>(q, adla);
    }

    // 4. bias tables + transpose
    biasprep<<<HEADS * ADLAV, 256>>>(an, na, ah, aw, ad, ha, wa, da, b1, b2);
    transpose_b2<<<dim3((NTOK + 31) / 32, (ADLAV + 31) / 32, HEADS), dim3(32, 8)>>>(b2, b2t);

    // 5. fused attn1: av = softmax(SCALE*(adla @ K^T) + bias1) @ V
    flash_ns<<<dim3((ADLAV + 127) / 128, BATCH * HEADS), 256, FSM>>>(
        adla, (long long)ADLAV * DIMV, HD, DIMV,
        kv,   (long long)NTOK * 2 * DIMV, HD, 2 * DIMV,
        kv,   (long long)NTOK * 2 * DIMV, HD, 2 * DIMV, DIMV,
        b1,   (long long)ADLAV * NTOK, NTOK,
        av,   (long long)HEADS * ADLAV * HD, (long long)ADLAV * HD, HD,
        ADLAV, NTOK);

    // 6. fused attn2: attnout = softmax(SCALE*(q @ adla^T) + bias2t) @ av
    flash_ns<<<dim3((NTOK + 127) / 128, BATCH * HEADS), 256, FSM>>>(
        q,    (long long)NTOK * DIMV, HD, DIMV,
        adla, (long long)ADLAV * DIMV, HD, DIMV,
        av,   (long long)HEADS * ADLAV * HD, (long long)ADLAV * HD, HD, 0,
        b2t,  (long long)NTOK * ADLAV, ADLAV,
        ao,   (long long)NTOK * DIMV, HD, DIMV,
        NTOK, ADLAV);

    // 7. depthwise conv 3x3x3 of v, added into attnout
    {
        long long tot = (long long)BATCH * NTOK * DIMV;
        dwc_add<<<(unsigned)((tot + 255) / 256), 256>>>(kv, dwcw, dwcb, ao);
    }

    // 8. final: out = attnout @ Wproj + bproj
    tgemm128<<<gT128(BN_TOT, DIMV), 256>>>(BN_TOT, DIMV, DIMV,
        ao,    DIMV, 1,
        Wproj, DIMV, 1,
        out,   DIMV, 1,
        bproj, 0, 1,
        1.f);

    (void)in_sizes; (void)n_in; (void)out_size;
}

// round 13
// speedup vs baseline: 1.8094x; 1.0796x over previous
#include <cuda_runtime.h>
#include <math.h>
#include <stdint.h>

#define HEADS   8
#define DIMV    384
#define HD      48
#define ADLAV   343
#define HWD     14
#define NTOK    2744
#define BATCH   8
#define SCALEV  0.14433756729740645f   // 48^-0.5
#define NSPLIT  8

#define BN_TOT  (BATCH * NTOK)         // 21952
#define BH      (BATCH * HEADS)        // 64

// ---------------- scratch (static device allocations) ------------------------
__device__ float g_q[BATCH * NTOK * DIMV];
__device__ float g_kv[BATCH * NTOK * 2 * DIMV];
__device__ float g_adla[BATCH * ADLAV * DIMV];
__device__ float g_bias1[HEADS * ADLAV * NTOK];
__device__ float g_bias2[HEADS * ADLAV * NTOK];      // [h,a,n]
__device__ float g_bias2t[HEADS * ADLAV * NTOK];     // [h,n,a]
__device__ float g_adlav[BATCH * HEADS * ADLAV * HD];
__device__ float g_avp[NSPLIT * BH * ADLAV * HD];    // split partial O~  (33.7MB)
__device__ float g_lsp[NSPLIT * BH * ADLAV];         // split partial rowsum
__device__ float g_attnout[BATCH * NTOK * DIMV];

// ---------------- tf32 helpers ----------------------------------------------
__device__ __forceinline__ uint32_t f2tf32(float x) {
    uint32_t r;
    asm("cvt.rna.tf32.f32 %0, %1;" : "=r"(r) : "f"(x));
    return r;
}

__device__ __forceinline__ void mma_tf32(float* c, const uint32_t* a, const uint32_t* b) {
    asm volatile(
        "mma.sync.aligned.m16n8k8.row.col.f32.tf32.tf32.f32 "
        "{%0,%1,%2,%3}, {%4,%5,%6,%7}, {%8,%9}, {%0,%1,%2,%3};\n"
        : "+f"(c[0]), "+f"(c[1]), "+f"(c[2]), "+f"(c[3])
        : "r"(a[0]), "r"(a[1]), "r"(a[2]), "r"(a[3]), "r"(b[0]), "r"(b[1]));
}

// ============ fused attention core (no max subtraction) ======================
// s = SCALE*(Q @ K^T) + bias per 64-key chunk; p~ = exp(s); O~ += p~ @ V;
// rowsums accumulated per-thread fp32. PARTIAL=1 writes unnormalized O~ and
// rowsums for a split-K slice (chunks split, split+NSPLIT, ...); PARTIAL=0
// processes all chunks and writes normalized O.
#define KSP 72
#define VSP 56
#define PSP 24
#define FSM ((48*KSP + 64*VSP + 8*64*PSP) * 4)

template<int PARTIAL>
__global__ __launch_bounds__(256) void flash_core(
    const float* __restrict__ Qp, long long qB, long long qH, int qR,
    const float* __restrict__ Kp, long long kB, long long kH, int kR,
    const float* __restrict__ Vp, long long vB, long long vH, int vR, int vC,
    const float* __restrict__ Bp, long long bHs, int bR,
    float* __restrict__ Op, long long oB, long long oH, int oR,
    float* __restrict__ Lp,
    int M, int NK)
{
    extern __shared__ float sm[];
    float* Ks = sm;                       // [48][KSP], d-major
    float* Vs = sm + 48 * KSP;            // [64][VSP], n-major
    float* Ps = sm + 48 * KSP + 64 * VSP; // 8 warps x [64][PSP]

    int bh = blockIdx.y;
    int bb = bh >> 3, hh = bh & 7;
    int m0 = blockIdx.x * 128;
    const float* Qb = Qp + bb * qB + hh * qH;
    const float* Kb = Kp + bb * kB + hh * kH;
    const float* Vb = Vp + bb * vB + hh * vH + vC;
    const float* Bb = Bp + hh * bHs;

    int tid = threadIdx.x, warp = tid >> 5, lane = tid & 31;
    int g = lane >> 2, tg = lane & 3;
    int r0 = m0 + warp * 16 + g;
    int r1 = r0 + 8;

    // Q fragments (unscaled tf32; SCALE applied after mma)
    uint32_t qf[6][4];
    #pragma unroll
    for (int ks = 0; ks < 6; ks++) {
        int k0 = ks * 8 + tg, k1 = k0 + 4;
        qf[ks][0] = (r0 < M) ? f2tf32(Qb[(long long)r0 * qR + k0]) : 0u;
        qf[ks][1] = (r1 < M) ? f2tf32(Qb[(long long)r1 * qR + k0]) : 0u;
        qf[ks][2] = (r0 < M) ? f2tf32(Qb[(long long)r0 * qR + k1]) : 0u;
        qf[ks][3] = (r1 < M) ? f2tf32(Qb[(long long)r1 * qR + k1]) : 0u;
    }

    float oacc[6][4];
    #pragma unroll
    for (int i = 0; i < 6; i++)
        #pragma unroll
        for (int j = 0; j < 4; j++) oacc[i][j] = 0.f;
    float rs0 = 0.f, rs1 = 0.f;

    float* Pw = Ps + warp * (64 * PSP);
    int nn = tid >> 2, f0 = tid & 3;
    int nch = (NK + 63) >> 6;

    int chBegin = PARTIAL ? (int)blockIdx.z : 0;
    int chStep  = PARTIAL ? NSPLIT : 1;

    for (int ch = chBegin; ch < nch; ch += chStep) {
        int n0 = ch * 64;
        int lim = min(64, NK - n0);

        // ---- load K chunk -> Ks[d][n], V chunk -> Vs[n][d] ----
        __syncthreads();
        #pragma unroll
        for (int j = 0; j < 3; j++) {
            int dbase = (f0 + j * 4) * 4;
            float4 v = make_float4(0.f, 0.f, 0.f, 0.f);
            float4 w = make_float4(0.f, 0.f, 0.f, 0.f);
            if (nn < lim) {
                v = *(const float4*)(Kb + (long long)(n0 + nn) * kR + dbase);
                w = *(const float4*)(Vb + (long long)(n0 + nn) * vR + dbase);
            }
            Ks[(dbase + 0) * KSP + nn] = __uint_as_float(f2tf32(v.x));
            Ks[(dbase + 1) * KSP + nn] = __uint_as_float(f2tf32(v.y));
            Ks[(dbase + 2) * KSP + nn] = __uint_as_float(f2tf32(v.z));
            Ks[(dbase + 3) * KSP + nn] = __uint_as_float(f2tf32(v.w));
            uint4 u;
            u.x = f2tf32(w.x); u.y = f2tf32(w.y); u.z = f2tf32(w.z); u.w = f2tf32(w.w);
            *(uint4*)&Vs[nn * VSP + dbase] = u;
        }
        __syncthreads();

        // ---- S = SCALE*(Q @ K^T) + bias ----
        float s[8][4];
        #pragma unroll
        for (int ni = 0; ni < 8; ni++)
            #pragma unroll
            for (int l = 0; l < 4; l++) s[ni][l] = 0.f;
        #pragma unroll
        for (int ks = 0; ks < 6; ks++) {
            #pragma unroll
            for (int ni = 0; ni < 8; ni++) {
                uint32_t bf[2];
                bf[0] = __float_as_uint(Ks[(ks * 8 + tg) * KSP + ni * 8 + g]);
                bf[1] = __float_as_uint(Ks[(ks * 8 + tg + 4) * KSP + ni * 8 + g]);
                mma_tf32(s[ni], qf[ks], bf);
            }
        }
        #pragma unroll
        for (int ni = 0; ni < 8; ni++) {
            int c0 = n0 + ni * 8 + 2 * tg;
            bool v0 = c0 < NK, v1 = (c0 + 1) < NK;
            float b00 = 0.f, b01 = 0.f, b10 = 0.f, b11 = 0.f;
            if (r0 < M) {
                if (v0) b00 = Bb[(long long)r0 * bR + c0];
                if (v1) b01 = Bb[(long long)r0 * bR + c0 + 1];
            }
            if (r1 < M) {
                if (v0) b10 = Bb[(long long)r1 * bR + c0];
                if (v1) b11 = Bb[(long long)r1 * bR + c0 + 1];
            }
            s[ni][0] = v0 ? SCALEV * s[ni][0] + b00 : -1e30f;
            s[ni][1] = v1 ? SCALEV * s[ni][1] + b01 : -1e30f;
            s[ni][2] = v0 ? SCALEV * s[ni][2] + b10 : -1e30f;
            s[ni][3] = v1 ? SCALEV * s[ni][3] + b11 : -1e30f;
        }

        // ---- exp (no max) + rowsum partials ----
        #pragma unroll
        for (int ni = 0; ni < 8; ni++) {
            float p0 = __expf(s[ni][0]);
            float p1 = __expf(s[ni][1]);
            float p2 = __expf(s[ni][2]);
            float p3 = __expf(s[ni][3]);
            s[ni][0] = p0; s[ni][1] = p1; s[ni][2] = p2; s[ni][3] = p3;
            rs0 += p0 + p1;
            rs1 += p2 + p3;
        }

        // ---- P -> warp-private smem ----
        #pragma unroll
        for (int ni = 0; ni < 8; ni++) {
            int c = ni * 8 + 2 * tg;
            Pw[c * PSP + g]           = __uint_as_float(f2tf32(s[ni][0]));
            Pw[(c + 1) * PSP + g]     = __uint_as_float(f2tf32(s[ni][1]));
            Pw[c * PSP + g + 8]       = __uint_as_float(f2tf32(s[ni][2]));
            Pw[(c + 1) * PSP + g + 8] = __uint_as_float(f2tf32(s[ni][3]));
        }
        __syncwarp();

        // ---- O~ += P @ V ----
        #pragma unroll
        for (int ks = 0; ks < 8; ks++) {
            uint32_t af[4];
            af[0] = __float_as_uint(Pw[(ks * 8 + tg) * PSP + g]);
            af[1] = __float_as_uint(Pw[(ks * 8 + tg) * PSP + g + 8]);
            af[2] = __float_as_uint(Pw[(ks * 8 + tg + 4) * PSP + g]);
            af[3] = __float_as_uint(Pw[(ks * 8 + tg + 4) * PSP + g + 8]);
            #pragma unroll
            for (int ni = 0; ni < 6; ni++) {
                uint32_t bf[2];
                bf[0] = __float_as_uint(Vs[(ks * 8 + tg) * VSP + ni * 8 + g]);
                bf[1] = __float_as_uint(Vs[(ks * 8 + tg + 4) * VSP + ni * 8 + g]);
                mma_tf32(oacc[ni], af, bf);
            }
        }
    }

    // ---- reduce rowsums over tg lanes ----
    rs0 += __shfl_xor_sync(0xffffffffu, rs0, 1);
    rs0 += __shfl_xor_sync(0xffffffffu, rs0, 2);
    rs1 += __shfl_xor_sync(0xffffffffu, rs1, 1);
    rs1 += __shfl_xor_sync(0xffffffffu, rs1, 2);

    if (PARTIAL) {
        // unnormalized partials: O~ rows + rowsums for this split
        long long rbase = ((long long)blockIdx.z * gridDim.y + bh) * M;
        float* Pop = Op + rbase * HD;   // [rows][HD], rows = M per (split,bh)
        float* Plp = Lp + rbase;
        #pragma unroll
        for (int ni = 0; ni < 6; ni++) {
            int d = ni * 8 + tg * 2;
            if (r0 < M) {
                float2 w; w.x = oacc[ni][0]; w.y = oacc[ni][1];
                *(float2*)(Pop + (long long)r0 * HD + d) = w;
            }
            if (r1 < M) {
                float2 w; w.x = oacc[ni][2]; w.y = oacc[ni][3];
                *(float2*)(Pop + (long long)r1 * HD + d) = w;
            }
        }
        if (tg == 0) {
            if (r0 < M) Plp[r0] = rs0;
            if (r1 < M) Plp[r1] = rs1;
        }
    } else {
        float* Ob = Op + bb * oB + hh * oH;
        float inv0 = 1.f / rs0;
        float inv1 = 1.f / rs1;
        #pragma unroll
        for (int ni = 0; ni < 6; ni++) {
            int d = ni * 8 + tg * 2;
            if (r0 < M) {
                float2 w; w.x = oacc[ni][0] * inv0; w.y = oacc[ni][1] * inv0;
                *(float2*)(Ob + (long long)r0 * oR + d) = w;
            }
            if (r1 < M) {
                float2 w; w.x = oacc[ni][2] * inv1; w.y = oacc[ni][3] * inv1;
                *(float2*)(Ob + (long long)r1 * oR + d) = w;
            }
        }
    }
}

// combine split partials (fixed order -> deterministic): av = sum O~ / sum l
__global__ void combine_av(const float* __restrict__ Pop,
                           const float* __restrict__ Plp,
                           float* __restrict__ av)
{
    long long t = (long long)blockIdx.x * blockDim.x + threadIdx.x;
    if (t >= (long long)BH * ADLAV * HD) return;
    int d = (int)(t % HD);
    long long ra = t / HD;               // bh*ADLAV + a
    float so = 0.f, sl = 0.f;
    #pragma unroll
    for (int s = 0; s < NSPLIT; s++) {
        so += Pop[((long long)s * BH * ADLAV + ra) * HD + d];
        sl += Plp[(long long)s * BH * ADLAV + ra];
    }
    av[t] = so / sl;
}

// ============ tgemm128: tile 128x128, BK=16 (projections, csB=1) =============
#define BMT 128
#define BNT2 128
#define BKT 16
#define PP  136
__global__ __launch_bounds__(256) void tgemm128(int M, int N, int K,
    const float* __restrict__ A, long long rsA, long long csA,
    const float* __restrict__ B, long long rsB, long long csB,
    float* __restrict__ C, long long rsC, long long csC,
    const float* __restrict__ Bi, long long rsBi, long long csBi,
    float alpha)
{
    __shared__ uint32_t As[2][BKT][PP];
    __shared__ uint32_t Bs[2][BKT][PP];

    const float* Ab = A;
    const float* Bb = B;
    float*       Cb = C;
    const float* Bib = Bi;

    int m0 = blockIdx.y * BMT;
    int n0 = blockIdx.x * BNT2;
    int tid  = threadIdx.x;
    int warp = tid >> 5;
    int lane = tid & 31;
    int g  = lane >> 2;
    int tg = lane & 3;
    int wm = warp & 1;
    int wn = warp >> 1;
    int mW = wm * 64;
    int nW = wn * 32;

    int amM = tid & 127;
    int akq = tid >> 7;
    const bool bContigN = (csB == 1);

    float acc[4][4][4];
    #pragma unroll
    for (int i = 0; i < 4; i++)
        #pragma unroll
        for (int j = 0; j < 4; j++)
            #pragma unroll
            for (int l = 0; l < 4; l++) acc[i][j][l] = 0.f;

    float4 va[2], vb[2];

    auto loadTile = [&](int k0) {
        #pragma unroll
        for (int i = 0; i < 2; i++) {
            int kq = akq + i * 2;
            int gm = m0 + amM, gk = k0 + kq * 4;
            float4 v = make_float4(0.f, 0.f, 0.f, 0.f);
            if (gm < M) {
                if (csA == 1 && gk + 4 <= K) {
                    v = *(const float4*)(Ab + (long long)gm * rsA + gk);
                } else {
                    float* pv = (float*)&v;
                    #pragma unroll
                    for (int j = 0; j < 4; j++)
                        if (gk + j < K) pv[j] = Ab[(long long)gm * rsA + (long long)(gk + j) * csA];
                }
            }
            va[i] = v;
        }
        #pragma unroll
        for (int i = 0; i < 2; i++) {
            int slot = tid + i * 256;
            float4 v = make_float4(0.f, 0.f, 0.f, 0.f);
            if (bContigN) {
                int kk = slot >> 5, nq = slot & 31;
                int gk = k0 + kk, gn = n0 + nq * 4;
                if (gk < K) {
                    if (gn + 4 <= N) {
                        v = *(const float4*)(Bb + (long long)gk * rsB + gn);
                    } else {
                        float* pv = (float*)&v;
                        #pragma unroll
                        for (int j = 0; j < 4; j++)
                            if (gn + j < N) pv[j] = Bb[(long long)gk * rsB + (long long)(gn + j)];
                    }
                }
            } else {
                int nnn = slot >> 2, kq2 = slot & 3;
                int gn = n0 + nnn, gk = k0 + kq2 * 4;
                if (gn < N) {
                    if (rsB == 1 && gk + 4 <= K) {
                        v = *(const float4*)(Bb + (long long)gn * csB + gk);
                    } else {
                        float* pv = (float*)&v;
                        #pragma unroll
                        for (int j = 0; j < 4; j++)
                            if (gk + j < K) pv[j] = Bb[(long long)(gk + j) * rsB + (long long)gn * csB];
                    }
                }
            }
            vb[i] = v;
        }
    };

    auto storeTile = [&](int bsel) {
        #pragma unroll
        for (int i = 0; i < 2; i++) {
            int kq = akq + i * 2;
            const float* pv = (const float*)&va[i];
            #pragma unroll
            for (int j = 0; j < 4; j++)
                As[bsel][kq * 4 + j][amM] = f2tf32(pv[j]);
        }
        #pragma unroll
        for (int i = 0; i < 2; i++) {
            int slot = tid + i * 256;
            const float* pv = (const float*)&vb[i];
            if (bContigN) {
                int kk = slot >> 5, nq = slot & 31;
                uint4 u;
                u.x = f2tf32(pv[0]); u.y = f2tf32(pv[1]);
                u.z = f2tf32(pv[2]); u.w = f2tf32(pv[3]);
                *(uint4*)&Bs[bsel][kk][nq * 4] = u;
            } else {
                int nnn = slot >> 2, kq2 = slot & 3;
                #pragma unroll
                for (int j = 0; j < 4; j++)
                    Bs[bsel][kq2 * 4 + j][nnn] = f2tf32(pv[j]);
            }
        }
    };

    auto compute = [&](int bsel) {
        #pragma unroll
        for (int ks = 0; ks < 2; ks++) {
            int kk = ks * 8;
            uint32_t af[4][4];
            #pragma unroll
            for (int mi = 0; mi < 4; mi++) {
                int mb = mW + mi * 16;
                af[mi][0] = As[bsel][kk + tg][mb + g];
                af[mi][1] = As[bsel][kk + tg][mb + g + 8];
                af[mi][2] = As[bsel][kk + tg + 4][mb + g];
                af[mi][3] = As[bsel][kk + tg + 4][mb + g + 8];
            }
            uint32_t bf[4][2];
            #pragma unroll
            for (int ni = 0; ni < 4; ni++) {
                int nb = nW + ni * 8;
                bf[ni][0] = Bs[bsel][kk + tg][nb + g];
                bf[ni][1] = Bs[bsel][kk + tg + 4][nb + g];
            }
            #pragma unroll
            for (int mi = 0; mi < 4; mi++)
                #pragma unroll
                for (int ni = 0; ni < 4; ni++)
                    mma_tf32(acc[mi][ni], af[mi], bf[ni]);
        }
    };

    int nk = (K + BKT - 1) / BKT;
    loadTile(0);
    storeTile(0);
    __syncthreads();
    int buf = 0;
    for (int i = 0; i < nk; i++) {
        if (i + 1 < nk) loadTile((i + 1) * BKT);
        compute(buf);
        if (i + 1 < nk) {
            storeTile(buf ^ 1);
            buf ^= 1;
            __syncthreads();
        }
    }

    bool vecC = (csC == 1) && ((rsC & 1) == 0);
    #pragma unroll
    for (int mi = 0; mi < 4; mi++) {
        #pragma unroll
        for (int ni = 0; ni < 4; ni++) {
            #pragma unroll
            for (int half = 0; half < 2; half++) {
                int r = m0 + mW + mi * 16 + g + half * 8;
                if (r >= M) continue;
                int c = n0 + nW + ni * 8 + tg * 2;
                float v0 = alpha * acc[mi][ni][half * 2];
                float v1 = alpha * acc[mi][ni][half * 2 + 1];
                if (Bib) {
                    if (c < N)     v0 += Bib[(long long)r * rsBi + (long long)c * csBi];
                    if (c + 1 < N) v1 += Bib[(long long)r * rsBi + (long long)(c + 1) * csBi];
                }
                if (vecC && c + 2 <= N) {
                    float2 w; w.x = v0; w.y = v1;
                    *(float2*)(Cb + (long long)r * rsC + c) = w;
                } else {
                    if (c < N)     Cb[(long long)r * rsC + (long long)c * csC] = v0;
                    if (c + 1 < N) Cb[(long long)r * rsC + (long long)(c + 1) * csC] = v1;
                }
            }
        }
    }
}

// ---------------- pooling ----------------------------------------------------
__global__ void pool_kernel(const float* __restrict__ q, float* __restrict__ adla)
{
    long long t = (long long)blockIdx.x * blockDim.x + threadIdx.x;
    if (t >= (long long)BATCH * ADLAV * DIMV) return;
    int c = (int)(t % DIMV);
    int a = (int)((t / DIMV) % ADLAV);
    int b = (int)(t / ((long long)DIMV * ADLAV));
    int p0 = a / 49, p1 = (a / 7) % 7, p2 = a % 7;
    float s = 0.f;
    #pragma unroll
    for (int r0 = 0; r0 < 2; r0++)
        #pragma unroll
        for (int r1 = 0; r1 < 2; r1++)
            #pragma unroll
            for (int r2 = 0; r2 < 2; r2++) {
                int i = p0 * 2 + r0, j = p1 * 2 + r1, k = p2 * 2 + r2;
                int n = (i * HWD + j) * HWD + k;
                s += q[((long long)b * NTOK + n) * DIMV + c];
            }
    adla[t] = s * 0.125f;
}

// ---------------- trilinear weights (7 -> 14) --------------------------------
__device__ __forceinline__ void lin_w(int o, int& x0, int& x1, float& w)
{
    float x = 0.5f * (float)o - 0.25f;
    x = fminf(fmaxf(x, 0.f), 6.f);
    x0 = (int)floorf(x);
    if (x0 > 6) x0 = 6;
    x1 = min(x0 + 1, 6);
    w = x - (float)x0;
}

__global__ void biasprep(const float* __restrict__ an, const float* __restrict__ na,
                         const float* __restrict__ ah, const float* __restrict__ aw,
                         const float* __restrict__ ad, const float* __restrict__ ha,
                         const float* __restrict__ wa, const float* __restrict__ da,
                         float* __restrict__ b1, float* __restrict__ b2)
{
    int haid = blockIdx.x;
    int h = haid / ADLAV;
    int a = haid % ADLAV;
    __shared__ float s_an[343], s_na[343];
    __shared__ float s_ax[3][14];
    __shared__ float s_xa[3][14];
    int tid = threadIdx.x;
    const float* anb = an + (long long)haid * 343;
    const float* nab = na + (long long)haid * 343;
    for (int i = tid; i < 343; i += 256) { s_an[i] = anb[i]; s_na[i] = nab[i]; }
    if (tid < 14) {
        s_ax[0][tid] = ah[(long long)haid * HWD + tid];
        s_ax[1][tid] = aw[(long long)haid * HWD + tid];
        s_ax[2][tid] = ad[(long long)haid * HWD + tid];
        s_xa[0][tid] = ha[((long long)h * HWD + tid) * ADLAV + a];
        s_xa[1][tid] = wa[((long long)h * HWD + tid) * ADLAV + a];
        s_xa[2][tid] = da[((long long)h * HWD + tid) * ADLAV + a];
    }
    __syncthreads();
    long long base = (long long)haid * NTOK;
    for (int n = tid; n < NTOK; n += 256) {
        int i = n / (HWD * HWD), j = (n / HWD) % HWD, k = n % HWD;
        int i0, i1, j0, j1, k0, k1;
        float wi, wj, wk;
        lin_w(i, i0, i1, wi);
        lin_w(j, j0, j1, wj);
        lin_w(k, k0, k1, wk);
        float v1, v2;
        {
            const float* t = s_an;
            float c00 = (1.f-wk)*t[(i0*7+j0)*7+k0] + wk*t[(i0*7+j0)*7+k1];
            float c01 = (1.f-wk)*t[(i0*7+j1)*7+k0] + wk*t[(i0*7+j1)*7+k1];
            float c10 = (1.f-wk)*t[(i1*7+j0)*7+k0] + wk*t[(i1*7+j0)*7+k1];
            float c11 = (1.f-wk)*t[(i1*7+j1)*7+k0] + wk*t[(i1*7+j1)*7+k1];
            v1 = (1.f-wi)*((1.f-wj)*c00 + wj*c01) + wi*((1.f-wj)*c10 + wj*c11);
        }
        {
            const float* t = s_na;
            float c00 = (1.f-wk)*t[(i0*7+j0)*7+k0] + wk*t[(i0*7+j0)*7+k1];
            float c01 = (1.f-wk)*t[(i0*7+j1)*7+k0] + wk*t[(i0*7+j1)*7+k1];
            float c10 = (1.f-wk)*t[(i1*7+j0)*7+k0] + wk*t[(i1*7+j0)*7+k1];
            float c11 = (1.f-wk)*t[(i1*7+j1)*7+k0] + wk*t[(i1*7+j1)*7+k1];
            v2 = (1.f-wi)*((1.f-wj)*c00 + wj*c01) + wi*((1.f-wj)*c10 + wj*c11);
        }
        v1 += s_ax[0][i] + s_ax[1][j] + s_ax[2][k];
        v2 += s_xa[0][i] + s_xa[1][j] + s_xa[2][k];
        b1[base + n] = v1;
        b2[base + n] = v2;
    }
}

// tiled transpose: b2[h,a,n] -> b2t[h,n,a]
__global__ void transpose_b2(const float* __restrict__ b2, float* __restrict__ b2t)
{
    __shared__ float t[32][33];
    int h = blockIdx.z;
    int a0 = blockIdx.y * 32, n0 = blockIdx.x * 32;
    int x = threadIdx.x, y = threadIdx.y;
    #pragma unroll
    for (int yy = y; yy < 32; yy += 8) {
        int a = a0 + yy, n = n0 + x;
        if (a < ADLAV && n < NTOK)
            t[yy][x] = b2[((long long)h * ADLAV + a) * NTOK + n];
    }
    __syncthreads();
    #pragma unroll
    for (int yy = y; yy < 32; yy += 8) {
        int n = n0 + yy, a = a0 + x;
        if (a < ADLAV && n < NTOK)
            b2t[((long long)h * NTOK + n) * ADLAV + a] = t[x][yy];
    }
}

// ---------------- depthwise 3x3x3 conv (SAME), add into out ------------------
__global__ void dwc_add(const float* __restrict__ kv, const float* __restrict__ w,
                        const float* __restrict__ bvec, float* __restrict__ out)
{
    long long t = (long long)blockIdx.x * blockDim.x + threadIdx.x;
    if (t >= (long long)BATCH * NTOK * DIMV) return;
    int c = (int)(t % DIMV);
    int n = (int)((t / DIMV) % NTOK);
    int b = (int)(t / ((long long)DIMV * NTOK));
    int i = n / (HWD * HWD), j = (n / HWD) % HWD, k = n % HWD;
    float acc = bvec[c];
    const float* wc = w + (long long)c * 27;
    #pragma unroll
    for (int di = -1; di <= 1; di++) {
        int ii = i + di;
        if (ii < 0 || ii >= HWD) continue;
        #pragma unroll
        for (int dj = -1; dj <= 1; dj++) {
            int jj = j + dj;
            if (jj < 0 || jj >= HWD) continue;
            #pragma unroll
            for (int dk = -1; dk <= 1; dk++) {
                int kk = k + dk;
                if (kk < 0 || kk >= HWD) continue;
                int nn = (ii * HWD + jj) * HWD + kk;
                acc += kv[((long long)b * NTOK + nn) * (2 * DIMV) + DIMV + c]
                     * wc[(di + 1) * 9 + (dj + 1) * 3 + (dk + 1)];
            }
        }
    }
    out[t] += acc;
}

// ---------------- host launcher ----------------------------------------------
static inline dim3 gT128(int M, int N) {
    return dim3((unsigned)((N + BNT2 - 1) / BNT2), (unsigned)((M + BMT - 1) / BMT), 1);
}

extern "C" void kernel_launch(void* const* d_in, const int* in_sizes, int n_in,
                              void* d_out, int out_size)
{
    const float* x     = (const float*)d_in[0];
    const float* Wq    = (const float*)d_in[1];
    const float* Wkv   = (const float*)d_in[2];
    const float* Wproj = (const float*)d_in[3];
    const float* bproj = (const float*)d_in[4];
    const float* dwcw  = (const float*)d_in[5];
    const float* dwcb  = (const float*)d_in[6];
    const float* an    = (const float*)d_in[7];
    const float* na    = (const float*)d_in[8];
    const float* ah    = (const float*)d_in[9];
    const float* aw    = (const float*)d_in[10];
    const float* ad    = (const float*)d_in[11];
    const float* ha    = (const float*)d_in[12];
    const float* wa    = (const float*)d_in[13];
    const float* da    = (const float*)d_in[14];
    float* out = (float*)d_out;

    void *pq, *pkv, *padla, *pb1, *pb2, *pb2t, *pav, *pavp, *plsp, *pao;
    cudaGetSymbolAddress(&pq, g_q);
    cudaGetSymbolAddress(&pkv, g_kv);
    cudaGetSymbolAddress(&padla, g_adla);
    cudaGetSymbolAddress(&pb1, g_bias1);
    cudaGetSymbolAddress(&pb2, g_bias2);
    cudaGetSymbolAddress(&pb2t, g_bias2t);
    cudaGetSymbolAddress(&pav, g_adlav);
    cudaGetSymbolAddress(&pavp, g_avp);
    cudaGetSymbolAddress(&plsp, g_lsp);
    cudaGetSymbolAddress(&pao, g_attnout);
    float* q    = (float*)pq;
    float* kv   = (float*)pkv;
    float* adla = (float*)padla;
    float* b1   = (float*)pb1;
    float* b2   = (float*)pb2;
    float* b2t  = (float*)pb2t;
    float* av   = (float*)pav;
    float* avp  = (float*)pavp;
    float* lsp  = (float*)plsp;
    float* ao   = (float*)pao;

    cudaFuncSetAttribute(flash_core<0>, cudaFuncAttributeMaxDynamicSharedMemorySize, FSM);
    cudaFuncSetAttribute(flash_core<1>, cudaFuncAttributeMaxDynamicSharedMemorySize, FSM);

    // 1. q = x @ Wq
    tgemm128<<<gT128(BN_TOT, DIMV), 256>>>(BN_TOT, DIMV, DIMV,
        x,  DIMV, 1,
        Wq, DIMV, 1,
        q,  DIMV, 1,
        nullptr, 0, 0, 1.f);

    // 2. kv = x @ Wkv
    tgemm128<<<gT128(BN_TOT, 2 * DIMV), 256>>>(BN_TOT, 2 * DIMV, DIMV,
        x,   DIMV,    1,
        Wkv, 2 * DIMV, 1,
        kv,  2 * DIMV, 1,
        nullptr, 0, 0, 1.f);

    // 3. adla pooling
    {
        long long tot = (long long)BATCH * ADLAV * DIMV;
        pool_kernel<<<(unsigned)((tot + 255) / 256), 256>>>(q, adla);
    }

    // 4. bias tables + transpose
    biasprep<<<HEADS * ADLAV, 256>>>(an, na, ah, aw, ad, ha, wa, da, b1, b2);
    transpose_b2<<<dim3((NTOK + 31) / 32, (ADLAV + 31) / 32, HEADS), dim3(32, 8)>>>(b2, b2t);

    // 5. fused attn1 (split-K over keys): partials then deterministic combine
    flash_core<1><<<dim3((ADLAV + 127) / 128, BH, NSPLIT), 256, FSM>>>(
        adla, (long long)ADLAV * DIMV, HD, DIMV,
        kv,   (long long)NTOK * 2 * DIMV, HD, 2 * DIMV,
        kv,   (long long)NTOK * 2 * DIMV, HD, 2 * DIMV, DIMV,
        b1,   (long long)ADLAV * NTOK, NTOK,
        avp,  0, 0, 0,
        lsp,
        ADLAV, NTOK);
    {
        long long tot = (long long)BH * ADLAV * HD;
        combine_av<<<(unsigned)((tot + 255) / 256), 256>>>(avp, lsp, av);
    }

    // 6. fused attn2: attnout = softmax(SCALE*(q @ adla^T) + bias2t) @ av
    flash_core<0><<<dim3((NTOK + 127) / 128, BH), 256, FSM>>>(
        q,    (long long)NTOK * DIMV, HD, DIMV,
        adla, (long long)ADLAV * DIMV, HD, DIMV,
        av,   (long long)HEADS * ADLAV * HD, (long long)ADLAV * HD, HD, 0,
        b2t,  (long long)NTOK * ADLAV, ADLAV,
        ao,   (long long)NTOK * DIMV, HD, DIMV,
        nullptr,
        NTOK, ADLAV);

    // 7. depthwise conv 3x3x3 of v, added into attnout
    {
        long long tot = (long long)BATCH * NTOK * DIMV;
        dwc_add<<<(unsigned)((tot + 255) / 256), 256>>>(kv, dwcw, dwcb, ao);
    }

    // 8. final: out = attnout @ Wproj + bproj
    tgemm128<<<gT128(BN_TOT, DIMV), 256>>>(BN_TOT, DIMV, DIMV,
        ao,    DIMV, 1,
        Wproj, DIMV, 1,
        out,   DIMV, 1,
        bproj, 0, 1,
        1.f);

    (void)in_sizes; (void)n_in; (void)out_size;
}